// round 8
// baseline (speedup 1.0000x reference)
#include <cuda_runtime.h>
#include <cuda_bf16.h>
#include <cstdint>

#define NN 100000
#define EE 600000
#define DD 128

#define SCAN_CHUNK 1024
#define NBLK_SCAN ((NN + SCAN_CHUNK - 1) / SCAN_CHUNK)   // 98

// Scratch (allocation-free: __device__ globals)
__device__ float g_hs[(size_t)NN * DD];   // layer-1 GEMM out: X @ W1 (raw)
__device__ float g_hs2[(size_t)NN * DD];  // layer-2 GEMM out: h1 @ W2 (raw)
__device__ float g_dinv[NN];
__device__ int   g_cnt[NN];               // in-degree (excl self loop)
__device__ int   g_rowptr[NN];            // CSR row starts
__device__ int   g_fill[NN];              // fill cursors
__device__ int   g_srcidx[EE];            // CSR column (src) indices
__device__ int   g_bsums[NBLK_SCAN];
__device__ int   g_is64;                  // edge_index dtype flag
__device__ uint4 g_Whi[2][2048];          // W hi bf16 [K=128][N=128] per layer
__device__ uint4 g_Wlo[2][2048];          // W lo bf16 per layer

// ---------------------------------------------------------------------------
__device__ __forceinline__ uint32_t smem_u32(const void* p) {
    uint32_t a;
    asm("{ .reg .u64 t; cvta.to.shared.u64 t, %1; cvt.u32.u64 %0, t; }"
        : "=r"(a) : "l"(p));
    return a;
}

#define LDMATRIX_X4(r0, r1, r2, r3, addr) \
    asm volatile("ldmatrix.sync.aligned.m8n8.x4.shared.b16 {%0,%1,%2,%3}, [%4];" \
                 : "=r"(r0), "=r"(r1), "=r"(r2), "=r"(r3) : "r"(addr))
#define LDMATRIX_X4_T(r0, r1, r2, r3, addr) \
    asm volatile("ldmatrix.sync.aligned.m8n8.x4.trans.shared.b16 {%0,%1,%2,%3}, [%4];" \
                 : "=r"(r0), "=r"(r1), "=r"(r2), "=r"(r3) : "r"(addr))
#define MMA_BF16(c, a, b) \
    asm volatile("mma.sync.aligned.m16n8k16.row.col.f32.bf16.bf16.f32 " \
                 "{%0,%1,%2,%3}, {%4,%5,%6,%7}, {%8,%9}, {%0,%1,%2,%3};" \
                 : "+f"((c)[0]), "+f"((c)[1]), "+f"((c)[2]), "+f"((c)[3]) \
                 : "r"((a)[0]), "r"((a)[1]), "r"((a)[2]), "r"((a)[3]), \
                   "r"((b)[0]), "r"((b)[1]))

__device__ __forceinline__ int load_edge(const void* ei, long long pos) {
    if (g_is64) return (int)((const long long*)ei)[pos];
    return ((const int*)ei)[pos];
}

__device__ __forceinline__ unsigned bf16_hi(float x) {
    return (unsigned)__bfloat16_as_ushort(__float2bfloat16_rn(x));
}

// ---------------------------------------------------------------------------
// Fused: zero g_cnt (whole grid) + dtype detection (block 0).
__global__ __launch_bounds__(1024)
void detect_zero_kernel(const int* __restrict__ w) {
    int i = blockIdx.x * 1024 + threadIdx.x;
    if (i < NN) g_cnt[i] = 0;
    if (blockIdx.x == 0) {
        __shared__ int s_any;
        if (threadIdx.x == 0) s_any = 0;
        __syncthreads();
        int acc = 0;
        for (int k = threadIdx.x; k < 4096; k += 1024)
            acc |= w[2 * (k * 137) + 1];
        if (acc) atomicOr(&s_any, 1);
        __syncthreads();
        if (threadIdx.x == 0) g_is64 = (s_any == 0) ? 1 : 0;
    }
}

__global__ void hist_kernel(const void* __restrict__ ei) {
    int e = blockIdx.x * blockDim.x + threadIdx.x;
    if (e >= EE) return;
    int d = load_edge(ei, (long long)EE + e);
    atomicAdd(&g_cnt[d], 1);
}

// Per-chunk exclusive scan (chunks of 1024 = 256 thr x 4), emits g_bsums.
__global__ __launch_bounds__(256)
void scan1_kernel() {
    __shared__ int s_warp[8];
    const int tid  = threadIdx.x;
    const int base = blockIdx.x * SCAN_CHUNK + tid * 4;

    int v0 = (base + 0 < NN) ? g_cnt[base + 0] : 0;
    int v1 = (base + 1 < NN) ? g_cnt[base + 1] : 0;
    int v2 = (base + 2 < NN) ? g_cnt[base + 2] : 0;
    int v3 = (base + 3 < NN) ? g_cnt[base + 3] : 0;
    int tsum = v0 + v1 + v2 + v3;

    int lane = tid & 31, wid = tid >> 5;
    int incl = tsum;
    #pragma unroll
    for (int o = 1; o < 32; o <<= 1) {
        int n = __shfl_up_sync(0xffffffffu, incl, o);
        if (lane >= o) incl += n;
    }
    if (lane == 31) s_warp[wid] = incl;
    __syncthreads();
    if (wid == 0) {
        int w = (lane < 8) ? s_warp[lane] : 0;
        int wi = w;
        #pragma unroll
        for (int o = 1; o < 8; o <<= 1) {
            int n = __shfl_up_sync(0xffffffffu, wi, o);
            if (lane >= o) wi += n;
        }
        if (lane < 8) s_warp[lane] = wi - w;
        if (lane == 7 && blockIdx.x < NBLK_SCAN) g_bsums[blockIdx.x] = wi;
    }
    __syncthreads();

    int off = s_warp[wid] + (incl - tsum);
    if (base + 0 < NN) g_rowptr[base + 0] = off;
    if (base + 1 < NN) g_rowptr[base + 1] = off + v0;
    if (base + 2 < NN) g_rowptr[base + 2] = off + v0 + v1;
    if (base + 3 < NN) g_rowptr[base + 3] = off + v0 + v1 + v2;
}

// Fused scan2+scan3: block-reduce bsums below own chunk, finalize rowptr/fill/dinv.
__global__ __launch_bounds__(256)
void scan23_kernel() {
    __shared__ int s_part[8];
    const int tid   = threadIdx.x;
    const int lane  = tid & 31, wid = tid >> 5;
    const int i     = blockIdx.x * 256 + tid;
    const int chunk = (blockIdx.x * 256) / SCAN_CHUNK;   // constant per block

    int partial = (tid < chunk) ? g_bsums[tid] : 0;      // chunk <= 97 < 256
    #pragma unroll
    for (int o = 16; o > 0; o >>= 1)
        partial += __shfl_down_sync(0xffffffffu, partial, o);
    if (lane == 0) s_part[wid] = partial;
    __syncthreads();
    int off = s_part[0] + s_part[1] + s_part[2] + s_part[3]
            + s_part[4] + s_part[5] + s_part[6] + s_part[7];

    if (i < NN) {
        int rp = g_rowptr[i] + off;
        g_rowptr[i] = rp;
        g_fill[i]   = rp;
        g_dinv[i]   = rsqrtf((float)(g_cnt[i] + 1));
    }
}

__global__ void fill_kernel(const void* __restrict__ ei) {
    int e = blockIdx.x * blockDim.x + threadIdx.x;
    if (e >= EE) return;
    int s = load_edge(ei, e);
    int d = load_edge(ei, (long long)EE + e);
    int pos = atomicAdd(&g_fill[d], 1);
    g_srcidx[pos] = s;
}

// ---------------------------------------------------------------------------
// W prep for BOTH layers: split fp32 [K=128][N=128] into bf16 hi/lo images.
__global__ void wprep_kernel(const float* __restrict__ W1,
                             const float* __restrict__ W2) {
    int t = blockIdx.x * blockDim.x + threadIdx.x;   // 4096 threads
    if (t >= 4096) return;
    int set = t >> 11;
    int u   = t & 2047;                              // k = u>>4, nchunk = u&15
    const float* wp = (set ? W2 : W1) + (u >> 4) * DD + (u & 15) * 8;
    unsigned hi[8], lo[8];
    #pragma unroll
    for (int j = 0; j < 8; j++) {
        float x = wp[j];
        __nv_bfloat16 h = __float2bfloat16_rn(x);
        float rem = x - __bfloat162float(h);
        __nv_bfloat16 l = __float2bfloat16_rn(rem);
        hi[j] = (unsigned)__bfloat16_as_ushort(h);
        lo[j] = (unsigned)__bfloat16_as_ushort(l);
    }
    g_Whi[set][u] = make_uint4(hi[0] | (hi[1] << 16), hi[2] | (hi[3] << 16),
                               hi[4] | (hi[5] << 16), hi[6] | (hi[7] << 16));
    g_Wlo[set][u] = make_uint4(lo[0] | (lo[1] << 16), lo[2] | (lo[3] << 16),
                               lo[4] | (lo[5] << 16), lo[6] | (lo[7] << 16));
}

// ---------------------------------------------------------------------------
// mma.sync split-bf16 GEMM: per CTA 128x128 tile, K=128.
// FUSED=false: input rows from Xf (fp32 global), layer 0, out -> g_hs.
// FUSED=true : input rows = CSR gather over g_hs (+b1, relu), layer 1,
//              out -> g_hs2. The 51MB h1 intermediate never exists.
#define XSTR 136
#define SM_XLO 34816
#define SM_WHI 69632
#define SM_WLO 104448
#define GEMM_SMEM 139264

template <bool FUSED>
__global__ __launch_bounds__(256, 1)
void gemm_bf16_kernel(const float* __restrict__ Xf,
                      const float* __restrict__ bvec, int layer) {
    extern __shared__ __align__(16) char sm[];
    const int tid  = threadIdx.x;
    const int warp = tid >> 5;
    const int lane = tid & 31;
    const int row0 = blockIdx.x * 128;

    // --- W images -> smem (padded rows) ---
    {
        #pragma unroll
        for (int i = 0; i < 8; i++) {
            int idx = tid + i * 256;
            int off = (idx >> 4) * (XSTR * 2) + (idx & 15) * 16;
            *(uint4*)(sm + SM_WHI + off) = g_Whi[layer][idx];
            *(uint4*)(sm + SM_WLO + off) = g_Wlo[layer][idx];
        }
    }

    if (!FUSED) {
        // --- X tile from global fp32 -> bf16 hi/lo, padded rows ---
        int r = tid >> 1;
        int khalf = (tid & 1) * 64;
        bool valid = (row0 + r) < NN;
        const float4* xp = (const float4*)(Xf + (size_t)(row0 + r) * DD);
        #pragma unroll
        for (int kb = 0; kb < 8; kb++) {
            int k = khalf + kb * 8;
            float4 a = valid ? xp[k >> 2] : make_float4(0.f, 0.f, 0.f, 0.f);
            float4 b = valid ? xp[(k >> 2) + 1] : make_float4(0.f, 0.f, 0.f, 0.f);
            float f[8] = {a.x, a.y, a.z, a.w, b.x, b.y, b.z, b.w};
            unsigned hi[8], lo[8];
            #pragma unroll
            for (int j = 0; j < 8; j++) {
                __nv_bfloat16 h = __float2bfloat16_rn(f[j]);
                float rem = f[j] - __bfloat162float(h);
                __nv_bfloat16 l = __float2bfloat16_rn(rem);
                hi[j] = (unsigned)__bfloat16_as_ushort(h);
                lo[j] = (unsigned)__bfloat16_as_ushort(l);
            }
            int off = r * (XSTR * 2) + k * 2;
            *(uint4*)(sm + off) =
                make_uint4(hi[0] | (hi[1] << 16), hi[2] | (hi[3] << 16),
                           hi[4] | (hi[5] << 16), hi[6] | (hi[7] << 16));
            *(uint4*)(sm + SM_XLO + off) =
                make_uint4(lo[0] | (lo[1] << 16), lo[2] | (lo[3] << 16),
                           lo[4] | (lo[5] << 16), lo[6] | (lo[7] << 16));
        }
    } else {
        // --- X tile = CSR gather of g_hs rows (+bias, relu), direct to hi/lo ---
        const float4* hs4 = (const float4*)g_hs;
        const float4 bv = ((const float4*)bvec)[lane];
        #pragma unroll 1
        for (int i = 0; i < 16; i++) {
            const int r  = warp * 16 + i;
            const int gr = row0 + r;
            float4 res = make_float4(0.f, 0.f, 0.f, 0.f);
            if (gr < NN) {
                const int start = g_rowptr[gr];
                const int n     = g_cnt[gr];
                const float di  = g_dinv[gr];
                float4 sv = hs4[(size_t)gr * 32 + lane];
                float4 acc = make_float4(sv.x * di, sv.y * di, sv.z * di, sv.w * di);
                int j = 0;
                for (; j + 4 <= n; j += 4) {
                    int s0 = g_srcidx[start + j + 0];
                    int s1 = g_srcidx[start + j + 1];
                    int s2 = g_srcidx[start + j + 2];
                    int s3 = g_srcidx[start + j + 3];
                    float d0 = g_dinv[s0], d1 = g_dinv[s1];
                    float d2 = g_dinv[s2], d3 = g_dinv[s3];
                    float4 v0 = hs4[(size_t)s0 * 32 + lane];
                    float4 v1 = hs4[(size_t)s1 * 32 + lane];
                    float4 v2 = hs4[(size_t)s2 * 32 + lane];
                    float4 v3 = hs4[(size_t)s3 * 32 + lane];
                    acc.x = fmaf(v0.x, d0, fmaf(v1.x, d1, fmaf(v2.x, d2, fmaf(v3.x, d3, acc.x))));
                    acc.y = fmaf(v0.y, d0, fmaf(v1.y, d1, fmaf(v2.y, d2, fmaf(v3.y, d3, acc.y))));
                    acc.z = fmaf(v0.z, d0, fmaf(v1.z, d1, fmaf(v2.z, d2, fmaf(v3.z, d3, acc.z))));
                    acc.w = fmaf(v0.w, d0, fmaf(v1.w, d1, fmaf(v2.w, d2, fmaf(v3.w, d3, acc.w))));
                }
                for (; j < n; j++) {
                    int s = g_srcidx[start + j];
                    float ds = g_dinv[s];
                    float4 v = hs4[(size_t)s * 32 + lane];
                    acc.x = fmaf(v.x, ds, acc.x);
                    acc.y = fmaf(v.y, ds, acc.y);
                    acc.z = fmaf(v.z, ds, acc.z);
                    acc.w = fmaf(v.w, ds, acc.w);
                }
                res.x = fmaxf(acc.x * di + bv.x, 0.f);
                res.y = fmaxf(acc.y * di + bv.y, 0.f);
                res.z = fmaxf(acc.z * di + bv.z, 0.f);
                res.w = fmaxf(acc.w * di + bv.w, 0.f);
            }
            // hi/lo bf16 split, store lane's 4 cols (8B) into padded smem row
            unsigned h0 = bf16_hi(res.x), h1 = bf16_hi(res.y);
            unsigned h2 = bf16_hi(res.z), h3 = bf16_hi(res.w);
            float r0f = res.x - __bfloat162float(__ushort_as_bfloat16((unsigned short)h0));
            float r1f = res.y - __bfloat162float(__ushort_as_bfloat16((unsigned short)h1));
            float r2f = res.z - __bfloat162float(__ushort_as_bfloat16((unsigned short)h2));
            float r3f = res.w - __bfloat162float(__ushort_as_bfloat16((unsigned short)h3));
            unsigned l0 = bf16_hi(r0f), l1 = bf16_hi(r1f);
            unsigned l2 = bf16_hi(r2f), l3 = bf16_hi(r3f);
            int off = r * (XSTR * 2) + lane * 8;
            *(uint2*)(sm + off) = make_uint2(h0 | (h1 << 16), h2 | (h3 << 16));
            *(uint2*)(sm + SM_XLO + off) = make_uint2(l0 | (l1 << 16), l2 | (l3 << 16));
        }
    }
    __syncthreads();

    const int m_base = (warp >> 1) * 32;
    const int n_base = (warp & 1) * 64;

    const uint32_t sbase = smem_u32(sm);
    const int a_row = (lane & 7) + ((lane >> 3) & 1) * 8;
    const int a_col = (lane >> 4) * 8;
    const int b_krow = (lane & 7) + ((lane >> 3) & 1) * 8;
    const int b_ncol = (lane >> 4) * 8;

    float acc[2][8][4];
    #pragma unroll
    for (int mt = 0; mt < 2; mt++)
        #pragma unroll
        for (int j = 0; j < 8; j++)
            #pragma unroll
            for (int q = 0; q < 4; q++) acc[mt][j][q] = 0.f;

    #pragma unroll 2
    for (int ks = 0; ks < 8; ks++) {
        const int k0 = ks * 16;
        uint32_t ahi[2][4], alo[2][4], bhi[8][2], blo[8][2];
        #pragma unroll
        for (int mt = 0; mt < 2; mt++) {
            uint32_t aoff = ((m_base + mt * 16 + a_row) * XSTR + k0 + a_col) * 2;
            LDMATRIX_X4(ahi[mt][0], ahi[mt][1], ahi[mt][2], ahi[mt][3], sbase + aoff);
            LDMATRIX_X4(alo[mt][0], alo[mt][1], alo[mt][2], alo[mt][3],
                        sbase + SM_XLO + aoff);
        }
        #pragma unroll
        for (int jp = 0; jp < 4; jp++) {
            uint32_t boff = ((k0 + b_krow) * XSTR + n_base + jp * 16 + b_ncol) * 2;
            LDMATRIX_X4_T(bhi[jp * 2][0], bhi[jp * 2][1],
                          bhi[jp * 2 + 1][0], bhi[jp * 2 + 1][1],
                          sbase + SM_WHI + boff);
            LDMATRIX_X4_T(blo[jp * 2][0], blo[jp * 2][1],
                          blo[jp * 2 + 1][0], blo[jp * 2 + 1][1],
                          sbase + SM_WLO + boff);
        }
        #pragma unroll
        for (int mt = 0; mt < 2; mt++)
            #pragma unroll
            for (int j = 0; j < 8; j++) {
                MMA_BF16(acc[mt][j], ahi[mt], bhi[j]);
                MMA_BF16(acc[mt][j], ahi[mt], blo[j]);
                MMA_BF16(acc[mt][j], alo[mt], bhi[j]);
            }
    }

    // --- epilogue: direct float2 stores (raw, no dinv) ---
    float* OUT = FUSED ? g_hs2 : g_hs;
    #pragma unroll
    for (int mt = 0; mt < 2; mt++) {
        int r0 = row0 + m_base + mt * 16 + (lane >> 2);
        int r1 = r0 + 8;
        #pragma unroll
        for (int j = 0; j < 8; j++) {
            int c = n_base + j * 8 + (lane & 3) * 2;
            if (r0 < NN)
                *(float2*)(OUT + (size_t)r0 * DD + c) =
                    make_float2(acc[mt][j][0], acc[mt][j][1]);
            if (r1 < NN)
                *(float2*)(OUT + (size_t)r1 * DD + c) =
                    make_float2(acc[mt][j][2], acc[mt][j][3]);
        }
    }
}

// ---------------------------------------------------------------------------
// Final gather: one warp per dst node over g_hs2; per-edge dinv[src] FMA,
// fused bias; fp32 out.
__global__ __launch_bounds__(256)
void gather_kernel(const float* __restrict__ bvec, float* __restrict__ out) {
    const int w    = (blockIdx.x * blockDim.x + threadIdx.x) >> 5;
    const int lane = threadIdx.x & 31;
    if (w >= NN) return;

    const float4* hs4 = (const float4*)g_hs2;
    const int start = g_rowptr[w];
    const int n     = g_cnt[w];
    const float di  = g_dinv[w];

    float4 sv = hs4[(size_t)w * 32 + lane];
    float4 acc = make_float4(sv.x * di, sv.y * di, sv.z * di, sv.w * di);

    int j = 0;
    for (; j + 4 <= n; j += 4) {
        int s0 = g_srcidx[start + j + 0];
        int s1 = g_srcidx[start + j + 1];
        int s2 = g_srcidx[start + j + 2];
        int s3 = g_srcidx[start + j + 3];
        float d0 = g_dinv[s0], d1 = g_dinv[s1], d2 = g_dinv[s2], d3 = g_dinv[s3];
        float4 v0 = hs4[(size_t)s0 * 32 + lane];
        float4 v1 = hs4[(size_t)s1 * 32 + lane];
        float4 v2 = hs4[(size_t)s2 * 32 + lane];
        float4 v3 = hs4[(size_t)s3 * 32 + lane];
        acc.x = fmaf(v0.x, d0, fmaf(v1.x, d1, fmaf(v2.x, d2, fmaf(v3.x, d3, acc.x))));
        acc.y = fmaf(v0.y, d0, fmaf(v1.y, d1, fmaf(v2.y, d2, fmaf(v3.y, d3, acc.y))));
        acc.z = fmaf(v0.z, d0, fmaf(v1.z, d1, fmaf(v2.z, d2, fmaf(v3.z, d3, acc.z))));
        acc.w = fmaf(v0.w, d0, fmaf(v1.w, d1, fmaf(v2.w, d2, fmaf(v3.w, d3, acc.w))));
    }
    for (; j < n; j++) {
        int s = g_srcidx[start + j];
        float ds = g_dinv[s];
        float4 v = hs4[(size_t)s * 32 + lane];
        acc.x = fmaf(v.x, ds, acc.x);
        acc.y = fmaf(v.y, ds, acc.y);
        acc.z = fmaf(v.z, ds, acc.z);
        acc.w = fmaf(v.w, ds, acc.w);
    }

    const float4 b = ((const float4*)bvec)[lane];
    float4 r;
    r.x = acc.x * di + b.x;
    r.y = acc.y * di + b.y;
    r.z = acc.z * di + b.z;
    r.w = acc.w * di + b.w;
    ((float4*)out)[(size_t)w * 32 + lane] = r;
}

// ---------------------------------------------------------------------------
extern "C" void kernel_launch(void* const* d_in, const int* in_sizes, int n_in,
                              void* d_out, int out_size) {
    const float* x  = (const float*)d_in[0];
    const float* W1 = (const float*)d_in[1];
    const float* b1 = (const float*)d_in[2];
    const float* W2 = (const float*)d_in[3];
    const float* b2 = (const float*)d_in[4];
    const void*  ei = d_in[5];
    float* out = (float*)d_out;

    (void)in_sizes; (void)n_in; (void)out_size;

    cudaFuncSetAttribute(gemm_bf16_kernel<false>,
                         cudaFuncAttributeMaxDynamicSharedMemorySize, GEMM_SMEM);
    cudaFuncSetAttribute(gemm_bf16_kernel<true>,
                         cudaFuncAttributeMaxDynamicSharedMemorySize, GEMM_SMEM);

    const int GEMM_BLOCKS   = (NN + 127) / 128;     // 782
    const int GATHER_BLOCKS = (NN * 32 + 255) / 256;

    // Fork a side stream (capture-legal event fork/join from the default stream).
    cudaStream_t s2;
    cudaStreamCreateWithFlags(&s2, cudaStreamNonBlocking);
    cudaEvent_t evFork, evJoin;
    cudaEventCreateWithFlags(&evFork, cudaEventDisableTiming);
    cudaEventCreateWithFlags(&evJoin, cudaEventDisableTiming);

    cudaEventRecord(evFork, 0);
    cudaStreamWaitEvent(s2, evFork, 0);

    // Branch B (s2): weight prep + GEMM-1 (independent of CSR/dinv)
    wprep_kernel<<<16, 256, 0, s2>>>(W1, W2);
    gemm_bf16_kernel<false><<<GEMM_BLOCKS, 256, GEMM_SMEM, s2>>>(x, nullptr, 0);

    // Branch A (default stream): CSR build
    detect_zero_kernel<<<(NN + 1023) / 1024, 1024>>>((const int*)ei);
    hist_kernel<<<(EE + 255) / 256, 256>>>(ei);
    scan1_kernel<<<NBLK_SCAN, 256>>>();
    scan23_kernel<<<(NN + 255) / 256, 256>>>();
    fill_kernel<<<(EE + 255) / 256, 256>>>(ei);

    // Join
    cudaEventRecord(evJoin, s2);
    cudaStreamWaitEvent(0, evJoin, 0);

    // Fused: gather-1 (+b1, relu) feeding GEMM-2 in smem; out -> g_hs2
    gemm_bf16_kernel<true><<<GEMM_BLOCKS, 256, GEMM_SMEM>>>(nullptr, b1, 1);

    // Final aggregation
    gather_kernel<<<GATHER_BLOCKS, 256>>>(b2, out);

    cudaEventDestroy(evFork);
    cudaEventDestroy(evJoin);
}

// round 9
// speedup vs baseline: 1.1913x; 1.1913x over previous
#include <cuda_runtime.h>
#include <cuda_bf16.h>
#include <cstdint>

#define NN 100000
#define EE 600000
#define DD 128

#define SCAN_CHUNK 1024
#define NBLK_SCAN ((NN + SCAN_CHUNK - 1) / SCAN_CHUNK)   // 98

// Scratch (allocation-free: __device__ globals)
__device__ float g_hs[(size_t)NN * DD];   // GEMM out (raw, no dinv)
__device__ float g_dinv[NN];
__device__ int   g_cnt[NN];               // in-degree (excl self loop)
__device__ int   g_rowptr[NN];            // CSR row starts
__device__ int   g_fill[NN];              // fill cursors
__device__ int   g_srcidx[EE];            // CSR column (src) indices
__device__ int   g_bsums[NBLK_SCAN];
__device__ int   g_is64;                  // edge_index dtype flag

// ---------------------------------------------------------------------------
__device__ __forceinline__ uint32_t smem_u32(const void* p) {
    uint32_t a;
    asm("{ .reg .u64 t; cvta.to.shared.u64 t, %1; cvt.u32.u64 %0, t; }"
        : "=r"(a) : "l"(p));
    return a;
}

#define PDL_TRIGGER() asm volatile("griddepcontrol.launch_dependents;" ::: "memory")
#define PDL_WAIT()    asm volatile("griddepcontrol.wait;" ::: "memory")

#define LDMATRIX_X4(r0, r1, r2, r3, addr) \
    asm volatile("ldmatrix.sync.aligned.m8n8.x4.shared.b16 {%0,%1,%2,%3}, [%4];" \
                 : "=r"(r0), "=r"(r1), "=r"(r2), "=r"(r3) : "r"(addr))
#define LDMATRIX_X4_T(r0, r1, r2, r3, addr) \
    asm volatile("ldmatrix.sync.aligned.m8n8.x4.trans.shared.b16 {%0,%1,%2,%3}, [%4];" \
                 : "=r"(r0), "=r"(r1), "=r"(r2), "=r"(r3) : "r"(addr))
#define MMA_BF16(c, a, b) \
    asm volatile("mma.sync.aligned.m16n8k16.row.col.f32.bf16.bf16.f32 " \
                 "{%0,%1,%2,%3}, {%4,%5,%6,%7}, {%8,%9}, {%0,%1,%2,%3};" \
                 : "+f"((c)[0]), "+f"((c)[1]), "+f"((c)[2]), "+f"((c)[3]) \
                 : "r"((a)[0]), "r"((a)[1]), "r"((a)[2]), "r"((a)[3]), \
                   "r"((b)[0]), "r"((b)[1]))

__device__ __forceinline__ int load_edge(const void* ei, long long pos) {
    if (g_is64) return (int)((const long long*)ei)[pos];
    return ((const int*)ei)[pos];
}

// ---------------------------------------------------------------------------
// Fused: zero g_cnt (whole grid) + dtype detection (block 0).
__global__ __launch_bounds__(1024)
void detect_zero_kernel(const int* __restrict__ w) {
    int i = blockIdx.x * 1024 + threadIdx.x;
    if (i < NN) g_cnt[i] = 0;
    if (blockIdx.x == 0) {
        __shared__ int s_any;
        if (threadIdx.x == 0) s_any = 0;
        __syncthreads();
        int acc = 0;
        for (int k = threadIdx.x; k < 4096; k += 1024)
            acc |= w[2 * (k * 137) + 1];
        if (acc) atomicOr(&s_any, 1);
        __syncthreads();
        if (threadIdx.x == 0) g_is64 = (s_any == 0) ? 1 : 0;
    }
}

__global__ void hist_kernel(const void* __restrict__ ei) {
    int e = blockIdx.x * blockDim.x + threadIdx.x;
    if (e >= EE) return;
    int d = load_edge(ei, (long long)EE + e);
    atomicAdd(&g_cnt[d], 1);
}

// Per-chunk exclusive scan (chunks of 1024 = 256 thr x 4), emits g_bsums.
__global__ __launch_bounds__(256)
void scan1_kernel() {
    __shared__ int s_warp[8];
    const int tid  = threadIdx.x;
    const int base = blockIdx.x * SCAN_CHUNK + tid * 4;

    int v0 = (base + 0 < NN) ? g_cnt[base + 0] : 0;
    int v1 = (base + 1 < NN) ? g_cnt[base + 1] : 0;
    int v2 = (base + 2 < NN) ? g_cnt[base + 2] : 0;
    int v3 = (base + 3 < NN) ? g_cnt[base + 3] : 0;
    int tsum = v0 + v1 + v2 + v3;

    int lane = tid & 31, wid = tid >> 5;
    int incl = tsum;
    #pragma unroll
    for (int o = 1; o < 32; o <<= 1) {
        int n = __shfl_up_sync(0xffffffffu, incl, o);
        if (lane >= o) incl += n;
    }
    if (lane == 31) s_warp[wid] = incl;
    __syncthreads();
    if (wid == 0) {
        int w = (lane < 8) ? s_warp[lane] : 0;
        int wi = w;
        #pragma unroll
        for (int o = 1; o < 8; o <<= 1) {
            int n = __shfl_up_sync(0xffffffffu, wi, o);
            if (lane >= o) wi += n;
        }
        if (lane < 8) s_warp[lane] = wi - w;
        if (lane == 7 && blockIdx.x < NBLK_SCAN) g_bsums[blockIdx.x] = wi;
    }
    __syncthreads();

    int off = s_warp[wid] + (incl - tsum);
    if (base + 0 < NN) g_rowptr[base + 0] = off;
    if (base + 1 < NN) g_rowptr[base + 1] = off + v0;
    if (base + 2 < NN) g_rowptr[base + 2] = off + v0 + v1;
    if (base + 3 < NN) g_rowptr[base + 3] = off + v0 + v1 + v2;
}

// Fused scan2+scan3: block-reduce bsums below own chunk, finalize rowptr/fill/dinv.
// Primary for fill_kernel (PDL): trigger at start.
__global__ __launch_bounds__(256)
void scan23_kernel() {
    PDL_TRIGGER();
    __shared__ int s_part[8];
    const int tid   = threadIdx.x;
    const int lane  = tid & 31, wid = tid >> 5;
    const int i     = blockIdx.x * 256 + tid;
    const int chunk = (blockIdx.x * 256) / SCAN_CHUNK;   // constant per block

    int partial = (tid < chunk) ? g_bsums[tid] : 0;      // chunk <= 97 < 256
    #pragma unroll
    for (int o = 16; o > 0; o >>= 1)
        partial += __shfl_down_sync(0xffffffffu, partial, o);
    if (lane == 0) s_part[wid] = partial;
    __syncthreads();
    int off = s_part[0] + s_part[1] + s_part[2] + s_part[3]
            + s_part[4] + s_part[5] + s_part[6] + s_part[7];

    if (i < NN) {
        int rp = g_rowptr[i] + off;
        g_rowptr[i] = rp;
        g_fill[i]   = rp;
        g_dinv[i]   = rsqrtf((float)(g_cnt[i] + 1));
    }
}

// Secondary of scan23 (PDL): loads edges (independent), waits, then scatters.
__global__ void fill_kernel(const void* __restrict__ ei) {
    int e = blockIdx.x * blockDim.x + threadIdx.x;
    if (e >= EE) { PDL_WAIT(); return; }
    int s = load_edge(ei, e);
    int d = load_edge(ei, (long long)EE + e);
    PDL_WAIT();                      // g_fill/g_rowptr valid after this
    int pos = atomicAdd(&g_fill[d], 1);
    g_srcidx[pos] = s;
}

// ---------------------------------------------------------------------------
// mma.sync split-bf16 GEMM: per CTA 128x128 tile, K=128.
// W converted fp32 -> bf16 hi/lo in-kernel (wprep eliminated).
// PDL=true (gemm2): trigger at start (primary for gather2), wait before X reads
// (secondary of gather1).
#define XSTR 136
#define SM_XLO 34816
#define SM_WHI 69632
#define SM_WLO 104448
#define GEMM_SMEM 139264

template <bool PDL>
__global__ __launch_bounds__(256, 1)
void gemm_bf16_kernel(const float* __restrict__ Xf, const float* __restrict__ Wf) {
    if (PDL) PDL_TRIGGER();
    extern __shared__ __align__(16) char sm[];
    const int tid  = threadIdx.x;
    const int warp = tid >> 5;
    const int lane = tid & 31;
    const int row0 = blockIdx.x * 128;

    // --- W fp32 [K=128][N=128] -> bf16 hi/lo smem images (padded rows) ---
    {
        const float4* wv = (const float4*)Wf;
        #pragma unroll
        for (int i = 0; i < 16; i++) {
            int idx = tid + i * 256;           // float4 index: k = idx>>5, nc = idx&31
            int k  = idx >> 5;
            int nc = idx & 31;
            float4 v = wv[idx];
            float f[4] = {v.x, v.y, v.z, v.w};
            unsigned hi[4], lo[4];
            #pragma unroll
            for (int j = 0; j < 4; j++) {
                __nv_bfloat16 h = __float2bfloat16_rn(f[j]);
                float rem = f[j] - __bfloat162float(h);
                __nv_bfloat16 l = __float2bfloat16_rn(rem);
                hi[j] = (unsigned)__bfloat16_as_ushort(h);
                lo[j] = (unsigned)__bfloat16_as_ushort(l);
            }
            int off = k * (XSTR * 2) + nc * 8;
            *(uint2*)(sm + SM_WHI + off) =
                make_uint2(hi[0] | (hi[1] << 16), hi[2] | (hi[3] << 16));
            *(uint2*)(sm + SM_WLO + off) =
                make_uint2(lo[0] | (lo[1] << 16), lo[2] | (lo[3] << 16));
        }
    }
    if (PDL) PDL_WAIT();             // Xf (h1) valid after this
    // --- X tile: fp32 -> bf16 hi/lo, padded rows ---
    {
        int r = tid >> 1;
        int khalf = (tid & 1) * 64;
        bool valid = (row0 + r) < NN;
        const float4* xp = (const float4*)(Xf + (size_t)(row0 + r) * DD);
        #pragma unroll
        for (int kb = 0; kb < 8; kb++) {
            int k = khalf + kb * 8;
            float4 a = valid ? xp[k >> 2] : make_float4(0.f, 0.f, 0.f, 0.f);
            float4 b = valid ? xp[(k >> 2) + 1] : make_float4(0.f, 0.f, 0.f, 0.f);
            float f[8] = {a.x, a.y, a.z, a.w, b.x, b.y, b.z, b.w};
            unsigned hi[8], lo[8];
            #pragma unroll
            for (int j = 0; j < 8; j++) {
                __nv_bfloat16 h = __float2bfloat16_rn(f[j]);
                float rem = f[j] - __bfloat162float(h);
                __nv_bfloat16 l = __float2bfloat16_rn(rem);
                hi[j] = (unsigned)__bfloat16_as_ushort(h);
                lo[j] = (unsigned)__bfloat16_as_ushort(l);
            }
            int off = r * (XSTR * 2) + k * 2;
            *(uint4*)(sm + off) =
                make_uint4(hi[0] | (hi[1] << 16), hi[2] | (hi[3] << 16),
                           hi[4] | (hi[5] << 16), hi[6] | (hi[7] << 16));
            *(uint4*)(sm + SM_XLO + off) =
                make_uint4(lo[0] | (lo[1] << 16), lo[2] | (lo[3] << 16),
                           lo[4] | (lo[5] << 16), lo[6] | (lo[7] << 16));
        }
    }
    __syncthreads();

    const int m_base = (warp >> 1) * 32;
    const int n_base = (warp & 1) * 64;

    const uint32_t sbase = smem_u32(sm);
    const int a_row = (lane & 7) + ((lane >> 3) & 1) * 8;
    const int a_col = (lane >> 4) * 8;
    const int b_krow = (lane & 7) + ((lane >> 3) & 1) * 8;
    const int b_ncol = (lane >> 4) * 8;

    float acc[2][8][4];
    #pragma unroll
    for (int mt = 0; mt < 2; mt++)
        #pragma unroll
        for (int j = 0; j < 8; j++)
            #pragma unroll
            for (int q = 0; q < 4; q++) acc[mt][j][q] = 0.f;

    #pragma unroll 2
    for (int ks = 0; ks < 8; ks++) {
        const int k0 = ks * 16;
        uint32_t ahi[2][4], alo[2][4], bhi[8][2], blo[8][2];
        #pragma unroll
        for (int mt = 0; mt < 2; mt++) {
            uint32_t aoff = ((m_base + mt * 16 + a_row) * XSTR + k0 + a_col) * 2;
            LDMATRIX_X4(ahi[mt][0], ahi[mt][1], ahi[mt][2], ahi[mt][3], sbase + aoff);
            LDMATRIX_X4(alo[mt][0], alo[mt][1], alo[mt][2], alo[mt][3],
                        sbase + SM_XLO + aoff);
        }
        #pragma unroll
        for (int jp = 0; jp < 4; jp++) {
            uint32_t boff = ((k0 + b_krow) * XSTR + n_base + jp * 16 + b_ncol) * 2;
            LDMATRIX_X4_T(bhi[jp * 2][0], bhi[jp * 2][1],
                          bhi[jp * 2 + 1][0], bhi[jp * 2 + 1][1],
                          sbase + SM_WHI + boff);
            LDMATRIX_X4_T(blo[jp * 2][0], blo[jp * 2][1],
                          blo[jp * 2 + 1][0], blo[jp * 2 + 1][1],
                          sbase + SM_WLO + boff);
        }
        #pragma unroll
        for (int mt = 0; mt < 2; mt++)
            #pragma unroll
            for (int j = 0; j < 8; j++) {
                MMA_BF16(acc[mt][j], ahi[mt], bhi[j]);
                MMA_BF16(acc[mt][j], ahi[mt], blo[j]);
                MMA_BF16(acc[mt][j], alo[mt], bhi[j]);
            }
    }

    // --- epilogue: direct float2 stores (raw, no dinv) ---
    #pragma unroll
    for (int mt = 0; mt < 2; mt++) {
        int r0 = row0 + m_base + mt * 16 + (lane >> 2);
        int r1 = r0 + 8;
        #pragma unroll
        for (int j = 0; j < 8; j++) {
            int c = n_base + j * 8 + (lane & 3) * 2;
            if (r0 < NN)
                *(float2*)(g_hs + (size_t)r0 * DD + c) =
                    make_float2(acc[mt][j][0], acc[mt][j][1]);
            if (r1 < NN)
                *(float2*)(g_hs + (size_t)r1 * DD + c) =
                    make_float2(acc[mt][j][2], acc[mt][j][3]);
        }
    }
}

// ---------------------------------------------------------------------------
// Gather: one warp per dst node; per-edge dinv[src] FMA, fused bias/relu.
// TRIG: primary of the next PDL kernel. WAIT: secondary (g_hs dependent).
template <bool RELU, bool TRIG, bool WAIT>
__global__ __launch_bounds__(256)
void gather_kernel(const float* __restrict__ bvec, float* __restrict__ out) {
    if (TRIG) PDL_TRIGGER();
    const int w    = (blockIdx.x * blockDim.x + threadIdx.x) >> 5;
    const int lane = threadIdx.x & 31;
    if (w >= NN) { if (WAIT) PDL_WAIT(); return; }

    // Independent prologue: CSR indices + degree data (not produced by primary)
    const int start = g_rowptr[w];
    const int n     = g_cnt[w];
    const float di  = g_dinv[w];
    const float4 b  = ((const float4*)bvec)[lane];

    if (WAIT) PDL_WAIT();            // g_hs (gemm2 output) valid after this

    const float4* hs4 = (const float4*)g_hs;
    float4 sv = hs4[(size_t)w * 32 + lane];
    float4 acc = make_float4(sv.x * di, sv.y * di, sv.z * di, sv.w * di);

    int j = 0;
    for (; j + 4 <= n; j += 4) {
        int s0 = g_srcidx[start + j + 0];
        int s1 = g_srcidx[start + j + 1];
        int s2 = g_srcidx[start + j + 2];
        int s3 = g_srcidx[start + j + 3];
        float d0 = g_dinv[s0], d1 = g_dinv[s1], d2 = g_dinv[s2], d3 = g_dinv[s3];
        float4 v0 = hs4[(size_t)s0 * 32 + lane];
        float4 v1 = hs4[(size_t)s1 * 32 + lane];
        float4 v2 = hs4[(size_t)s2 * 32 + lane];
        float4 v3 = hs4[(size_t)s3 * 32 + lane];
        acc.x = fmaf(v0.x, d0, fmaf(v1.x, d1, fmaf(v2.x, d2, fmaf(v3.x, d3, acc.x))));
        acc.y = fmaf(v0.y, d0, fmaf(v1.y, d1, fmaf(v2.y, d2, fmaf(v3.y, d3, acc.y))));
        acc.z = fmaf(v0.z, d0, fmaf(v1.z, d1, fmaf(v2.z, d2, fmaf(v3.z, d3, acc.z))));
        acc.w = fmaf(v0.w, d0, fmaf(v1.w, d1, fmaf(v2.w, d2, fmaf(v3.w, d3, acc.w))));
    }
    for (; j < n; j++) {
        int s = g_srcidx[start + j];
        float ds = g_dinv[s];
        float4 v = hs4[(size_t)s * 32 + lane];
        acc.x = fmaf(v.x, ds, acc.x);
        acc.y = fmaf(v.y, ds, acc.y);
        acc.z = fmaf(v.z, ds, acc.z);
        acc.w = fmaf(v.w, ds, acc.w);
    }

    float4 r;
    r.x = acc.x * di + b.x;
    r.y = acc.y * di + b.y;
    r.z = acc.z * di + b.z;
    r.w = acc.w * di + b.w;
    if (RELU) {
        r.x = fmaxf(r.x, 0.f);
        r.y = fmaxf(r.y, 0.f);
        r.z = fmaxf(r.z, 0.f);
        r.w = fmaxf(r.w, 0.f);
    }
    ((float4*)out)[(size_t)w * 32 + lane] = r;
}

// ---------------------------------------------------------------------------
extern "C" void kernel_launch(void* const* d_in, const int* in_sizes, int n_in,
                              void* d_out, int out_size) {
    const float* x  = (const float*)d_in[0];
    const float* W1 = (const float*)d_in[1];
    const float* b1 = (const float*)d_in[2];
    const float* W2 = (const float*)d_in[3];
    const float* b2 = (const float*)d_in[4];
    const void*  ei = d_in[5];
    float* out = (float*)d_out;

    (void)in_sizes; (void)n_in; (void)out_size;

    cudaFuncSetAttribute(gemm_bf16_kernel<false>,
                         cudaFuncAttributeMaxDynamicSharedMemorySize, GEMM_SMEM);
    cudaFuncSetAttribute(gemm_bf16_kernel<true>,
                         cudaFuncAttributeMaxDynamicSharedMemorySize, GEMM_SMEM);

    const int GEMM_BLOCKS   = (NN + 127) / 128;     // 782
    const int GATHER_BLOCKS = (NN * 32 + 255) / 256;

    // PDL (programmatic stream serialization) launch attribute
    cudaLaunchAttribute pss[1];
    pss[0].id = cudaLaunchAttributeProgrammaticStreamSerialization;
    pss[0].val.programmaticStreamSerializationAllowed = 1;

    // Fork a side stream (capture-legal event fork/join from the default stream).
    cudaStream_t s2;
    cudaStreamCreateWithFlags(&s2, cudaStreamNonBlocking);
    cudaEvent_t evFork, evJoin;
    cudaEventCreateWithFlags(&evFork, cudaEventDisableTiming);
    cudaEventCreateWithFlags(&evJoin, cudaEventDisableTiming);

    cudaEventRecord(evFork, 0);
    cudaStreamWaitEvent(s2, evFork, 0);

    // Branch B (s2): GEMM-1 (independent of CSR/dinv; W converted in-kernel)
    gemm_bf16_kernel<false><<<GEMM_BLOCKS, 256, GEMM_SMEM, s2>>>(x, W1);

    // Branch A (default stream): CSR build
    detect_zero_kernel<<<(NN + 1023) / 1024, 1024>>>((const int*)ei);
    hist_kernel<<<(EE + 255) / 256, 256>>>(ei);
    scan1_kernel<<<NBLK_SCAN, 256>>>();
    scan23_kernel<<<(NN + 255) / 256, 256>>>();
    {   // fill: PDL secondary of scan23
        cudaLaunchConfig_t cfg = {};
        cfg.gridDim  = dim3((EE + 255) / 256);
        cfg.blockDim = dim3(256);
        cfg.stream   = 0;
        cfg.attrs    = pss;
        cfg.numAttrs = 1;
        cudaLaunchKernelEx(&cfg, fill_kernel, ei);
    }

    // Join
    cudaEventRecord(evJoin, s2);
    cudaStreamWaitEvent(0, evJoin, 0);

    // gather-1: triggers gemm2's programmatic launch
    gather_kernel<true, true, false><<<GATHER_BLOCKS, 256>>>(b1, out);

    {   // gemm2: PDL secondary of gather1 (W prologue overlaps), primary of gather2
        cudaLaunchConfig_t cfg = {};
        cfg.gridDim  = dim3(GEMM_BLOCKS);
        cfg.blockDim = dim3(256);
        cfg.dynamicSmemBytes = GEMM_SMEM;
        cfg.stream   = 0;
        cfg.attrs    = pss;
        cfg.numAttrs = 1;
        cudaLaunchKernelEx(&cfg, gemm_bf16_kernel<true>, (const float*)out,
                           (const float*)W2);
    }
    {   // gather2: PDL secondary of gemm2 (index prologue overlaps)
        cudaLaunchConfig_t cfg = {};
        cfg.gridDim  = dim3(GATHER_BLOCKS);
        cfg.blockDim = dim3(256);
        cfg.stream   = 0;
        cfg.attrs    = pss;
        cfg.numAttrs = 1;
        cudaLaunchKernelEx(&cfg, gather_kernel<false, false, true>,
                           (const float*)b2, (float*)out);
    }

    cudaEventDestroy(evFork);
    cudaEventDestroy(evJoin);
}

// round 10
// speedup vs baseline: 1.3165x; 1.1051x over previous
#include <cuda_runtime.h>
#include <cuda_bf16.h>
#include <cstdint>

#define NN 100000
#define EE 600000
#define DD 128

#define SCAN_CHUNK 1024
#define NBLK_SCAN ((NN + SCAN_CHUNK - 1) / SCAN_CHUNK)   // 98

// Scratch (allocation-free: __device__ globals)
__device__ float g_hs[(size_t)NN * DD];   // GEMM out (raw, no dinv)
__device__ float g_dinv[NN];
__device__ int   g_cnt[NN];               // in-degree (excl self loop)
__device__ int   g_rowptr[NN];            // CSR row starts
__device__ int   g_fill[NN];              // fill cursors
__device__ int   g_srcidx[EE];            // CSR column (src) indices
__device__ int   g_agg[NBLK_SCAN];        // lookback aggregates (total+1; 0 = not ready)
__device__ int   g_is64;                  // edge_index dtype flag

// ---------------------------------------------------------------------------
__device__ __forceinline__ uint32_t smem_u32(const void* p) {
    uint32_t a;
    asm("{ .reg .u64 t; cvta.to.shared.u64 t, %1; cvt.u32.u64 %0, t; }"
        : "=r"(a) : "l"(p));
    return a;
}

#define LDMATRIX_X4(r0, r1, r2, r3, addr) \
    asm volatile("ldmatrix.sync.aligned.m8n8.x4.shared.b16 {%0,%1,%2,%3}, [%4];" \
                 : "=r"(r0), "=r"(r1), "=r"(r2), "=r"(r3) : "r"(addr))
#define LDMATRIX_X4_T(r0, r1, r2, r3, addr) \
    asm volatile("ldmatrix.sync.aligned.m8n8.x4.trans.shared.b16 {%0,%1,%2,%3}, [%4];" \
                 : "=r"(r0), "=r"(r1), "=r"(r2), "=r"(r3) : "r"(addr))
#define MMA_BF16(c, a, b) \
    asm volatile("mma.sync.aligned.m16n8k16.row.col.f32.bf16.bf16.f32 " \
                 "{%0,%1,%2,%3}, {%4,%5,%6,%7}, {%8,%9}, {%0,%1,%2,%3};" \
                 : "+f"((c)[0]), "+f"((c)[1]), "+f"((c)[2]), "+f"((c)[3]) \
                 : "r"((a)[0]), "r"((a)[1]), "r"((a)[2]), "r"((a)[3]), \
                   "r"((b)[0]), "r"((b)[1]))

__device__ __forceinline__ int load_edge(const void* ei, long long pos) {
    if (g_is64) return (int)((const long long*)ei)[pos];
    return ((const int*)ei)[pos];
}

// ---------------------------------------------------------------------------
// Fused: zero g_cnt + lookback flags (whole grid) + dtype detection (block 0).
__global__ __launch_bounds__(1024)
void detect_zero_kernel(const int* __restrict__ w) {
    int i = blockIdx.x * 1024 + threadIdx.x;
    if (i < NN) g_cnt[i] = 0;
    if (i < NBLK_SCAN) g_agg[i] = 0;
    if (blockIdx.x == 0) {
        __shared__ int s_any;
        if (threadIdx.x == 0) s_any = 0;
        __syncthreads();
        int acc = 0;
        for (int k = threadIdx.x; k < 4096; k += 1024)
            acc |= w[2 * (k * 137) + 1];
        if (acc) atomicOr(&s_any, 1);
        __syncthreads();
        if (threadIdx.x == 0) g_is64 = (s_any == 0) ? 1 : 0;
    }
}

__global__ void hist_kernel(const void* __restrict__ ei) {
    int e = blockIdx.x * blockDim.x + threadIdx.x;
    if (e >= EE) return;
    int d = load_edge(ei, (long long)EE + e);
    atomicAdd(&g_cnt[d], 1);
}

// Fused exclusive scan (decoupled aggregates): 98 blocks, one wave, each block
// scans its 1024-chunk, publishes its aggregate, warp-0 spin-sums predecessor
// aggregates lane-parallel, then finalizes rowptr/fill/dinv directly.
__global__ __launch_bounds__(256)
void scan_fused_kernel() {
    __shared__ int s_warp[8];
    __shared__ int s_bexcl;
    const int tid  = threadIdx.x;
    const int lane = tid & 31, wid = tid >> 5;
    const int base = blockIdx.x * SCAN_CHUNK + tid * 4;

    int v0 = (base + 0 < NN) ? g_cnt[base + 0] : 0;
    int v1 = (base + 1 < NN) ? g_cnt[base + 1] : 0;
    int v2 = (base + 2 < NN) ? g_cnt[base + 2] : 0;
    int v3 = (base + 3 < NN) ? g_cnt[base + 3] : 0;
    int tsum = v0 + v1 + v2 + v3;

    int incl = tsum;
    #pragma unroll
    for (int o = 1; o < 32; o <<= 1) {
        int n = __shfl_up_sync(0xffffffffu, incl, o);
        if (lane >= o) incl += n;
    }
    if (lane == 31) s_warp[wid] = incl;
    __syncthreads();
    if (wid == 0) {
        int w = (lane < 8) ? s_warp[lane] : 0;
        int wi = w;
        #pragma unroll
        for (int o = 1; o < 8; o <<= 1) {
            int n = __shfl_up_sync(0xffffffffu, wi, o);
            if (lane >= o) wi += n;
        }
        if (lane < 8) s_warp[lane] = wi - w;
        int btot = __shfl_sync(0xffffffffu, wi, 7);      // block total
        if (lane == 0) atomicExch(&g_agg[blockIdx.x], btot + 1);

        // Lane-parallel lookback over predecessors (all blocks resident: grid=98)
        int sum = 0;
        for (int p = lane; p < blockIdx.x; p += 32) {
            int v;
            do { v = atomicAdd(&g_agg[p], 0); } while (v == 0);
            sum += v - 1;
        }
        #pragma unroll
        for (int o = 16; o > 0; o >>= 1)
            sum += __shfl_down_sync(0xffffffffu, sum, o);
        if (lane == 0) s_bexcl = sum;
    }
    __syncthreads();

    int off = s_bexcl + s_warp[wid] + (incl - tsum);
    int o0 = off, o1 = off + v0, o2 = o1 + v1, o3 = o2 + v2;
    if (base + 0 < NN) { g_rowptr[base+0] = o0; g_fill[base+0] = o0; g_dinv[base+0] = rsqrtf((float)(v0 + 1)); }
    if (base + 1 < NN) { g_rowptr[base+1] = o1; g_fill[base+1] = o1; g_dinv[base+1] = rsqrtf((float)(v1 + 1)); }
    if (base + 2 < NN) { g_rowptr[base+2] = o2; g_fill[base+2] = o2; g_dinv[base+2] = rsqrtf((float)(v2 + 1)); }
    if (base + 3 < NN) { g_rowptr[base+3] = o3; g_fill[base+3] = o3; g_dinv[base+3] = rsqrtf((float)(v3 + 1)); }
}

__global__ void fill_kernel(const void* __restrict__ ei) {
    int e = blockIdx.x * blockDim.x + threadIdx.x;
    if (e >= EE) return;
    int s = load_edge(ei, e);
    int d = load_edge(ei, (long long)EE + e);
    int pos = atomicAdd(&g_fill[d], 1);
    g_srcidx[pos] = s;
}

// ---------------------------------------------------------------------------
// mma.sync split-bf16 GEMM: per CTA 128x128 tile, K=128.
// W converted fp32 -> bf16 hi/lo in-kernel (no wprep kernel).
// g_hs[r,:] = X[r,:] @ W  (raw; dinv applied in gather)
#define XSTR 136
#define SM_XLO 34816
#define SM_WHI 69632
#define SM_WLO 104448
#define GEMM_SMEM 139264

__global__ __launch_bounds__(256, 1)
void gemm_bf16_kernel(const float* __restrict__ Xf, const float* __restrict__ Wf) {
    extern __shared__ __align__(16) char sm[];
    const int tid  = threadIdx.x;
    const int warp = tid >> 5;
    const int lane = tid & 31;
    const int row0 = blockIdx.x * 128;

    // --- W fp32 [K=128][N=128] -> bf16 hi/lo smem images (padded rows) ---
    {
        const float4* wv = (const float4*)Wf;
        #pragma unroll
        for (int i = 0; i < 16; i++) {
            int idx = tid + i * 256;           // float4 index: k = idx>>5, nc = idx&31
            int k  = idx >> 5;
            int nc = idx & 31;
            float4 v = wv[idx];
            float f[4] = {v.x, v.y, v.z, v.w};
            unsigned hi[4], lo[4];
            #pragma unroll
            for (int j = 0; j < 4; j++) {
                __nv_bfloat16 h = __float2bfloat16_rn(f[j]);
                float rem = f[j] - __bfloat162float(h);
                __nv_bfloat16 l = __float2bfloat16_rn(rem);
                hi[j] = (unsigned)__bfloat16_as_ushort(h);
                lo[j] = (unsigned)__bfloat16_as_ushort(l);
            }
            int off = k * (XSTR * 2) + nc * 8;
            *(uint2*)(sm + SM_WHI + off) =
                make_uint2(hi[0] | (hi[1] << 16), hi[2] | (hi[3] << 16));
            *(uint2*)(sm + SM_WLO + off) =
                make_uint2(lo[0] | (lo[1] << 16), lo[2] | (lo[3] << 16));
        }
    }
    // --- X tile: fp32 -> bf16 hi/lo, padded rows ---
    {
        int r = tid >> 1;
        int khalf = (tid & 1) * 64;
        bool valid = (row0 + r) < NN;
        const float4* xp = (const float4*)(Xf + (size_t)(row0 + r) * DD);
        #pragma unroll
        for (int kb = 0; kb < 8; kb++) {
            int k = khalf + kb * 8;
            float4 a = valid ? xp[k >> 2] : make_float4(0.f, 0.f, 0.f, 0.f);
            float4 b = valid ? xp[(k >> 2) + 1] : make_float4(0.f, 0.f, 0.f, 0.f);
            float f[8] = {a.x, a.y, a.z, a.w, b.x, b.y, b.z, b.w};
            unsigned hi[8], lo[8];
            #pragma unroll
            for (int j = 0; j < 8; j++) {
                __nv_bfloat16 h = __float2bfloat16_rn(f[j]);
                float rem = f[j] - __bfloat162float(h);
                __nv_bfloat16 l = __float2bfloat16_rn(rem);
                hi[j] = (unsigned)__bfloat16_as_ushort(h);
                lo[j] = (unsigned)__bfloat16_as_ushort(l);
            }
            int off = r * (XSTR * 2) + k * 2;
            *(uint4*)(sm + off) =
                make_uint4(hi[0] | (hi[1] << 16), hi[2] | (hi[3] << 16),
                           hi[4] | (hi[5] << 16), hi[6] | (hi[7] << 16));
            *(uint4*)(sm + SM_XLO + off) =
                make_uint4(lo[0] | (lo[1] << 16), lo[2] | (lo[3] << 16),
                           lo[4] | (lo[5] << 16), lo[6] | (lo[7] << 16));
        }
    }
    __syncthreads();

    const int m_base = (warp >> 1) * 32;
    const int n_base = (warp & 1) * 64;

    const uint32_t sbase = smem_u32(sm);
    const int a_row = (lane & 7) + ((lane >> 3) & 1) * 8;
    const int a_col = (lane >> 4) * 8;
    const int b_krow = (lane & 7) + ((lane >> 3) & 1) * 8;
    const int b_ncol = (lane >> 4) * 8;

    float acc[2][8][4];
    #pragma unroll
    for (int mt = 0; mt < 2; mt++)
        #pragma unroll
        for (int j = 0; j < 8; j++)
            #pragma unroll
            for (int q = 0; q < 4; q++) acc[mt][j][q] = 0.f;

    #pragma unroll 2
    for (int ks = 0; ks < 8; ks++) {
        const int k0 = ks * 16;
        uint32_t ahi[2][4], alo[2][4], bhi[8][2], blo[8][2];
        #pragma unroll
        for (int mt = 0; mt < 2; mt++) {
            uint32_t aoff = ((m_base + mt * 16 + a_row) * XSTR + k0 + a_col) * 2;
            LDMATRIX_X4(ahi[mt][0], ahi[mt][1], ahi[mt][2], ahi[mt][3], sbase + aoff);
            LDMATRIX_X4(alo[mt][0], alo[mt][1], alo[mt][2], alo[mt][3],
                        sbase + SM_XLO + aoff);
        }
        #pragma unroll
        for (int jp = 0; jp < 4; jp++) {
            uint32_t boff = ((k0 + b_krow) * XSTR + n_base + jp * 16 + b_ncol) * 2;
            LDMATRIX_X4_T(bhi[jp * 2][0], bhi[jp * 2][1],
                          bhi[jp * 2 + 1][0], bhi[jp * 2 + 1][1],
                          sbase + SM_WHI + boff);
            LDMATRIX_X4_T(blo[jp * 2][0], blo[jp * 2][1],
                          blo[jp * 2 + 1][0], blo[jp * 2 + 1][1],
                          sbase + SM_WLO + boff);
        }
        #pragma unroll
        for (int mt = 0; mt < 2; mt++)
            #pragma unroll
            for (int j = 0; j < 8; j++) {
                MMA_BF16(acc[mt][j], ahi[mt], bhi[j]);
                MMA_BF16(acc[mt][j], ahi[mt], blo[j]);
                MMA_BF16(acc[mt][j], alo[mt], bhi[j]);
            }
    }

    // --- epilogue: direct float2 stores (raw, no dinv) ---
    #pragma unroll
    for (int mt = 0; mt < 2; mt++) {
        int r0 = row0 + m_base + mt * 16 + (lane >> 2);
        int r1 = r0 + 8;
        #pragma unroll
        for (int j = 0; j < 8; j++) {
            int c = n_base + j * 8 + (lane & 3) * 2;
            if (r0 < NN)
                *(float2*)(g_hs + (size_t)r0 * DD + c) =
                    make_float2(acc[mt][j][0], acc[mt][j][1]);
            if (r1 < NN)
                *(float2*)(g_hs + (size_t)r1 * DD + c) =
                    make_float2(acc[mt][j][2], acc[mt][j][3]);
        }
    }
}

// ---------------------------------------------------------------------------
// Gather: one warp per dst node; per-edge dinv[src] FMA, fused bias/relu.
template <bool RELU>
__global__ __launch_bounds__(256)
void gather_kernel(const float* __restrict__ bvec, float* __restrict__ out) {
    const int w    = (blockIdx.x * blockDim.x + threadIdx.x) >> 5;
    const int lane = threadIdx.x & 31;
    if (w >= NN) return;

    const float4* hs4 = (const float4*)g_hs;
    const int start = g_rowptr[w];
    const int n     = g_cnt[w];
    const float di  = g_dinv[w];

    float4 sv = hs4[(size_t)w * 32 + lane];   // self loop
    float4 acc = make_float4(sv.x * di, sv.y * di, sv.z * di, sv.w * di);

    int j = 0;
    for (; j + 4 <= n; j += 4) {
        int s0 = g_srcidx[start + j + 0];
        int s1 = g_srcidx[start + j + 1];
        int s2 = g_srcidx[start + j + 2];
        int s3 = g_srcidx[start + j + 3];
        float d0 = g_dinv[s0], d1 = g_dinv[s1], d2 = g_dinv[s2], d3 = g_dinv[s3];
        float4 v0 = hs4[(size_t)s0 * 32 + lane];
        float4 v1 = hs4[(size_t)s1 * 32 + lane];
        float4 v2 = hs4[(size_t)s2 * 32 + lane];
        float4 v3 = hs4[(size_t)s3 * 32 + lane];
        acc.x = fmaf(v0.x, d0, fmaf(v1.x, d1, fmaf(v2.x, d2, fmaf(v3.x, d3, acc.x))));
        acc.y = fmaf(v0.y, d0, fmaf(v1.y, d1, fmaf(v2.y, d2, fmaf(v3.y, d3, acc.y))));
        acc.z = fmaf(v0.z, d0, fmaf(v1.z, d1, fmaf(v2.z, d2, fmaf(v3.z, d3, acc.z))));
        acc.w = fmaf(v0.w, d0, fmaf(v1.w, d1, fmaf(v2.w, d2, fmaf(v3.w, d3, acc.w))));
    }
    for (; j < n; j++) {
        int s = g_srcidx[start + j];
        float ds = g_dinv[s];
        float4 v = hs4[(size_t)s * 32 + lane];
        acc.x = fmaf(v.x, ds, acc.x);
        acc.y = fmaf(v.y, ds, acc.y);
        acc.z = fmaf(v.z, ds, acc.z);
        acc.w = fmaf(v.w, ds, acc.w);
    }

    const float4 b = ((const float4*)bvec)[lane];
    float4 r;
    r.x = acc.x * di + b.x;
    r.y = acc.y * di + b.y;
    r.z = acc.z * di + b.z;
    r.w = acc.w * di + b.w;
    if (RELU) {
        r.x = fmaxf(r.x, 0.f);
        r.y = fmaxf(r.y, 0.f);
        r.z = fmaxf(r.z, 0.f);
        r.w = fmaxf(r.w, 0.f);
    }
    ((float4*)out)[(size_t)w * 32 + lane] = r;
}

// ---------------------------------------------------------------------------
extern "C" void kernel_launch(void* const* d_in, const int* in_sizes, int n_in,
                              void* d_out, int out_size) {
    const float* x  = (const float*)d_in[0];
    const float* W1 = (const float*)d_in[1];
    const float* b1 = (const float*)d_in[2];
    const float* W2 = (const float*)d_in[3];
    const float* b2 = (const float*)d_in[4];
    const void*  ei = d_in[5];
    float* out = (float*)d_out;

    (void)in_sizes; (void)n_in; (void)out_size;

    cudaFuncSetAttribute(gemm_bf16_kernel,
                         cudaFuncAttributeMaxDynamicSharedMemorySize, GEMM_SMEM);

    const int GEMM_BLOCKS   = (NN + 127) / 128;     // 782
    const int GATHER_BLOCKS = (NN * 32 + 255) / 256;

    // Fork a side stream (capture-legal event fork/join from the default stream).
    cudaStream_t s2;
    cudaStreamCreateWithFlags(&s2, cudaStreamNonBlocking);
    cudaEvent_t evFork, evJoin;
    cudaEventCreateWithFlags(&evFork, cudaEventDisableTiming);
    cudaEventCreateWithFlags(&evJoin, cudaEventDisableTiming);

    cudaEventRecord(evFork, 0);
    cudaStreamWaitEvent(s2, evFork, 0);

    // Branch B (s2): GEMM-1 (independent of CSR/dinv; W converted in-kernel)
    gemm_bf16_kernel<<<GEMM_BLOCKS, 256, GEMM_SMEM, s2>>>(x, W1);

    // Branch A (default stream): CSR build
    detect_zero_kernel<<<(NN + 1023) / 1024, 1024>>>((const int*)ei);
    hist_kernel<<<(EE + 255) / 256, 256>>>(ei);
    scan_fused_kernel<<<NBLK_SCAN, 256>>>();
    fill_kernel<<<(EE + 255) / 256, 256>>>(ei);

    // Join
    cudaEventRecord(evJoin, s2);
    cudaStreamWaitEvent(0, evJoin, 0);

    // Layer 1 aggregation, then layer 2 (sequential by data dependence)
    gather_kernel<true><<<GATHER_BLOCKS, 256>>>(b1, out);
    gemm_bf16_kernel<<<GEMM_BLOCKS, 256, GEMM_SMEM>>>(out, W2);
    gather_kernel<false><<<GATHER_BLOCKS, 256>>>(b2, out);

    cudaEventDestroy(evFork);
    cudaEventDestroy(evJoin);
}

// round 11
// speedup vs baseline: 1.4310x; 1.0870x over previous
#include <cuda_runtime.h>
#include <cuda_bf16.h>
#include <cuda_fp16.h>
#include <cstdint>

#define NN 100000
#define EE 600000
#define DD 128

#define SCAN_CHUNK 1024
#define NBLK_SCAN ((NN + SCAN_CHUNK - 1) / SCAN_CHUNK)   // 98

// Scratch (allocation-free: __device__ globals)
__device__ __half g_hs16[(size_t)NN * DD]; // GEMM out (raw, no dinv), fp16
__device__ __half g_h1[(size_t)NN * DD];   // layer-1 activations (post relu), fp16
__device__ float g_dinv[NN];
__device__ int   g_cnt[NN];               // in-degree (excl self loop)
__device__ int   g_rowptr[NN];            // CSR row starts
__device__ int   g_fill[NN];              // fill cursors
__device__ int   g_srcidx[EE];            // CSR column (src) indices
__device__ int   g_agg[NBLK_SCAN];        // lookback aggregates (total+1; 0 = not ready)
__device__ int   g_is64;                  // edge_index dtype flag

// ---------------------------------------------------------------------------
__device__ __forceinline__ uint32_t smem_u32(const void* p) {
    uint32_t a;
    asm("{ .reg .u64 t; cvta.to.shared.u64 t, %1; cvt.u32.u64 %0, t; }"
        : "=r"(a) : "l"(p));
    return a;
}

#define LDMATRIX_X4(r0, r1, r2, r3, addr) \
    asm volatile("ldmatrix.sync.aligned.m8n8.x4.shared.b16 {%0,%1,%2,%3}, [%4];" \
                 : "=r"(r0), "=r"(r1), "=r"(r2), "=r"(r3) : "r"(addr))
#define LDMATRIX_X4_T(r0, r1, r2, r3, addr) \
    asm volatile("ldmatrix.sync.aligned.m8n8.x4.trans.shared.b16 {%0,%1,%2,%3}, [%4];" \
                 : "=r"(r0), "=r"(r1), "=r"(r2), "=r"(r3) : "r"(addr))
#define MMA_BF16(c, a, b) \
    asm volatile("mma.sync.aligned.m16n8k16.row.col.f32.bf16.bf16.f32 " \
                 "{%0,%1,%2,%3}, {%4,%5,%6,%7}, {%8,%9}, {%0,%1,%2,%3};" \
                 : "+f"((c)[0]), "+f"((c)[1]), "+f"((c)[2]), "+f"((c)[3]) \
                 : "r"((a)[0]), "r"((a)[1]), "r"((a)[2]), "r"((a)[3]), \
                   "r"((b)[0]), "r"((b)[1]))

__device__ __forceinline__ int load_edge(const void* ei, long long pos) {
    if (g_is64) return (int)((const long long*)ei)[pos];
    return ((const int*)ei)[pos];
}

// Accumulate 8 fp16 cols (uint4) scaled by d into acc[8]
__device__ __forceinline__ void acc8(float* acc, uint4 u, float d) {
    float2 p0 = __half22float2(*(__half2*)&u.x);
    float2 p1 = __half22float2(*(__half2*)&u.y);
    float2 p2 = __half22float2(*(__half2*)&u.z);
    float2 p3 = __half22float2(*(__half2*)&u.w);
    acc[0] = fmaf(p0.x, d, acc[0]);
    acc[1] = fmaf(p0.y, d, acc[1]);
    acc[2] = fmaf(p1.x, d, acc[2]);
    acc[3] = fmaf(p1.y, d, acc[3]);
    acc[4] = fmaf(p2.x, d, acc[4]);
    acc[5] = fmaf(p2.y, d, acc[5]);
    acc[6] = fmaf(p3.x, d, acc[6]);
    acc[7] = fmaf(p3.y, d, acc[7]);
}

// ---------------------------------------------------------------------------
// Fused: zero g_cnt + lookback flags (whole grid) + dtype detection (block 0).
__global__ __launch_bounds__(1024)
void detect_zero_kernel(const int* __restrict__ w) {
    int i = blockIdx.x * 1024 + threadIdx.x;
    if (i < NN) g_cnt[i] = 0;
    if (i < NBLK_SCAN) g_agg[i] = 0;
    if (blockIdx.x == 0) {
        __shared__ int s_any;
        if (threadIdx.x == 0) s_any = 0;
        __syncthreads();
        int acc = 0;
        for (int k = threadIdx.x; k < 4096; k += 1024)
            acc |= w[2 * (k * 137) + 1];
        if (acc) atomicOr(&s_any, 1);
        __syncthreads();
        if (threadIdx.x == 0) g_is64 = (s_any == 0) ? 1 : 0;
    }
}

__global__ void hist_kernel(const void* __restrict__ ei) {
    int e = blockIdx.x * blockDim.x + threadIdx.x;
    if (e >= EE) return;
    int d = load_edge(ei, (long long)EE + e);
    atomicAdd(&g_cnt[d], 1);
}

// Fused exclusive scan (decoupled aggregates), finalizes rowptr/fill/dinv.
__global__ __launch_bounds__(256)
void scan_fused_kernel() {
    __shared__ int s_warp[8];
    __shared__ int s_bexcl;
    const int tid  = threadIdx.x;
    const int lane = tid & 31, wid = tid >> 5;
    const int base = blockIdx.x * SCAN_CHUNK + tid * 4;

    int v0 = (base + 0 < NN) ? g_cnt[base + 0] : 0;
    int v1 = (base + 1 < NN) ? g_cnt[base + 1] : 0;
    int v2 = (base + 2 < NN) ? g_cnt[base + 2] : 0;
    int v3 = (base + 3 < NN) ? g_cnt[base + 3] : 0;
    int tsum = v0 + v1 + v2 + v3;

    int incl = tsum;
    #pragma unroll
    for (int o = 1; o < 32; o <<= 1) {
        int n = __shfl_up_sync(0xffffffffu, incl, o);
        if (lane >= o) incl += n;
    }
    if (lane == 31) s_warp[wid] = incl;
    __syncthreads();
    if (wid == 0) {
        int w = (lane < 8) ? s_warp[lane] : 0;
        int wi = w;
        #pragma unroll
        for (int o = 1; o < 8; o <<= 1) {
            int n = __shfl_up_sync(0xffffffffu, wi, o);
            if (lane >= o) wi += n;
        }
        if (lane < 8) s_warp[lane] = wi - w;
        int btot = __shfl_sync(0xffffffffu, wi, 7);
        if (lane == 0) atomicExch(&g_agg[blockIdx.x], btot + 1);

        int sum = 0;
        for (int p = lane; p < blockIdx.x; p += 32) {
            int v;
            do { v = atomicAdd(&g_agg[p], 0); } while (v == 0);
            sum += v - 1;
        }
        #pragma unroll
        for (int o = 16; o > 0; o >>= 1)
            sum += __shfl_down_sync(0xffffffffu, sum, o);
        if (lane == 0) s_bexcl = sum;
    }
    __syncthreads();

    int off = s_bexcl + s_warp[wid] + (incl - tsum);
    int o0 = off, o1 = off + v0, o2 = o1 + v1, o3 = o2 + v2;
    if (base + 0 < NN) { g_rowptr[base+0] = o0; g_fill[base+0] = o0; g_dinv[base+0] = rsqrtf((float)(v0 + 1)); }
    if (base + 1 < NN) { g_rowptr[base+1] = o1; g_fill[base+1] = o1; g_dinv[base+1] = rsqrtf((float)(v1 + 1)); }
    if (base + 2 < NN) { g_rowptr[base+2] = o2; g_fill[base+2] = o2; g_dinv[base+2] = rsqrtf((float)(v2 + 1)); }
    if (base + 3 < NN) { g_rowptr[base+3] = o3; g_fill[base+3] = o3; g_dinv[base+3] = rsqrtf((float)(v3 + 1)); }
}

__global__ void fill_kernel(const void* __restrict__ ei) {
    int e = blockIdx.x * blockDim.x + threadIdx.x;
    if (e >= EE) return;
    int s = load_edge(ei, e);
    int d = load_edge(ei, (long long)EE + e);
    int pos = atomicAdd(&g_fill[d], 1);
    g_srcidx[pos] = s;
}

// ---------------------------------------------------------------------------
// mma.sync split-bf16 GEMM: per CTA 128x128 tile, K=128.
// IN_F16=false: input Xf (fp32 global).  IN_F16=true: input g_h1 (fp16).
// Output: g_hs16 (fp16, raw; dinv applied in gather). W converted in-kernel.
#define XSTR 136
#define SM_XLO 34816
#define SM_WHI 69632
#define SM_WLO 104448
#define GEMM_SMEM 139264

template <bool IN_F16>
__global__ __launch_bounds__(256, 1)
void gemm_bf16_kernel(const float* __restrict__ Xf, const float* __restrict__ Wf) {
    extern __shared__ __align__(16) char sm[];
    const int tid  = threadIdx.x;
    const int warp = tid >> 5;
    const int lane = tid & 31;
    const int row0 = blockIdx.x * 128;

    // --- W fp32 [K=128][N=128] -> bf16 hi/lo smem images (padded rows) ---
    {
        const float4* wv = (const float4*)Wf;
        #pragma unroll
        for (int i = 0; i < 16; i++) {
            int idx = tid + i * 256;
            int k  = idx >> 5;
            int nc = idx & 31;
            float4 v = wv[idx];
            float f[4] = {v.x, v.y, v.z, v.w};
            unsigned hi[4], lo[4];
            #pragma unroll
            for (int j = 0; j < 4; j++) {
                __nv_bfloat16 h = __float2bfloat16_rn(f[j]);
                float rem = f[j] - __bfloat162float(h);
                __nv_bfloat16 l = __float2bfloat16_rn(rem);
                hi[j] = (unsigned)__bfloat16_as_ushort(h);
                lo[j] = (unsigned)__bfloat16_as_ushort(l);
            }
            int off = k * (XSTR * 2) + nc * 8;
            *(uint2*)(sm + SM_WHI + off) =
                make_uint2(hi[0] | (hi[1] << 16), hi[2] | (hi[3] << 16));
            *(uint2*)(sm + SM_WLO + off) =
                make_uint2(lo[0] | (lo[1] << 16), lo[2] | (lo[3] << 16));
        }
    }
    // --- X tile -> bf16 hi/lo, padded rows ---
    {
        int r = tid >> 1;
        int khalf = (tid & 1) * 64;
        bool valid = (row0 + r) < NN;
        #pragma unroll
        for (int kb = 0; kb < 8; kb++) {
            int k = khalf + kb * 8;
            float f[8];
            if (!IN_F16) {
                const float4* xp = (const float4*)(Xf + (size_t)(row0 + r) * DD);
                float4 a = valid ? xp[k >> 2] : make_float4(0.f, 0.f, 0.f, 0.f);
                float4 b = valid ? xp[(k >> 2) + 1] : make_float4(0.f, 0.f, 0.f, 0.f);
                f[0]=a.x; f[1]=a.y; f[2]=a.z; f[3]=a.w;
                f[4]=b.x; f[5]=b.y; f[6]=b.z; f[7]=b.w;
            } else {
                const uint4* hp = (const uint4*)(g_h1 + (size_t)(row0 + r) * DD);
                uint4 u = valid ? hp[k >> 3] : make_uint4(0u, 0u, 0u, 0u);
                unsigned uu[4] = {u.x, u.y, u.z, u.w};
                #pragma unroll
                for (int q = 0; q < 4; q++) {
                    float2 p = __half22float2(*(__half2*)&uu[q]);
                    f[q * 2] = p.x; f[q * 2 + 1] = p.y;
                }
            }
            unsigned hi[8], lo[8];
            #pragma unroll
            for (int j = 0; j < 8; j++) {
                __nv_bfloat16 h = __float2bfloat16_rn(f[j]);
                float rem = f[j] - __bfloat162float(h);
                __nv_bfloat16 l = __float2bfloat16_rn(rem);
                hi[j] = (unsigned)__bfloat16_as_ushort(h);
                lo[j] = (unsigned)__bfloat16_as_ushort(l);
            }
            int off = r * (XSTR * 2) + k * 2;
            *(uint4*)(sm + off) =
                make_uint4(hi[0] | (hi[1] << 16), hi[2] | (hi[3] << 16),
                           hi[4] | (hi[5] << 16), hi[6] | (hi[7] << 16));
            *(uint4*)(sm + SM_XLO + off) =
                make_uint4(lo[0] | (lo[1] << 16), lo[2] | (lo[3] << 16),
                           lo[4] | (lo[5] << 16), lo[6] | (lo[7] << 16));
        }
    }
    __syncthreads();

    const int m_base = (warp >> 1) * 32;
    const int n_base = (warp & 1) * 64;

    const uint32_t sbase = smem_u32(sm);
    const int a_row = (lane & 7) + ((lane >> 3) & 1) * 8;
    const int a_col = (lane >> 4) * 8;
    const int b_krow = (lane & 7) + ((lane >> 3) & 1) * 8;
    const int b_ncol = (lane >> 4) * 8;

    float acc[2][8][4];
    #pragma unroll
    for (int mt = 0; mt < 2; mt++)
        #pragma unroll
        for (int j = 0; j < 8; j++)
            #pragma unroll
            for (int q = 0; q < 4; q++) acc[mt][j][q] = 0.f;

    #pragma unroll 2
    for (int ks = 0; ks < 8; ks++) {
        const int k0 = ks * 16;
        uint32_t ahi[2][4], alo[2][4], bhi[8][2], blo[8][2];
        #pragma unroll
        for (int mt = 0; mt < 2; mt++) {
            uint32_t aoff = ((m_base + mt * 16 + a_row) * XSTR + k0 + a_col) * 2;
            LDMATRIX_X4(ahi[mt][0], ahi[mt][1], ahi[mt][2], ahi[mt][3], sbase + aoff);
            LDMATRIX_X4(alo[mt][0], alo[mt][1], alo[mt][2], alo[mt][3],
                        sbase + SM_XLO + aoff);
        }
        #pragma unroll
        for (int jp = 0; jp < 4; jp++) {
            uint32_t boff = ((k0 + b_krow) * XSTR + n_base + jp * 16 + b_ncol) * 2;
            LDMATRIX_X4_T(bhi[jp * 2][0], bhi[jp * 2][1],
                          bhi[jp * 2 + 1][0], bhi[jp * 2 + 1][1],
                          sbase + SM_WHI + boff);
            LDMATRIX_X4_T(blo[jp * 2][0], blo[jp * 2][1],
                          blo[jp * 2 + 1][0], blo[jp * 2 + 1][1],
                          sbase + SM_WLO + boff);
        }
        #pragma unroll
        for (int mt = 0; mt < 2; mt++)
            #pragma unroll
            for (int j = 0; j < 8; j++) {
                MMA_BF16(acc[mt][j], ahi[mt], bhi[j]);
                MMA_BF16(acc[mt][j], ahi[mt], blo[j]);
                MMA_BF16(acc[mt][j], alo[mt], bhi[j]);
            }
    }

    // --- epilogue: fp16 half2 stores (raw, no dinv) ---
    #pragma unroll
    for (int mt = 0; mt < 2; mt++) {
        int r0 = row0 + m_base + mt * 16 + (lane >> 2);
        int r1 = r0 + 8;
        #pragma unroll
        for (int j = 0; j < 8; j++) {
            int c = n_base + j * 8 + (lane & 3) * 2;
            if (r0 < NN)
                *(__half2*)(g_hs16 + (size_t)r0 * DD + c) =
                    __floats2half2_rn(acc[mt][j][0], acc[mt][j][1]);
            if (r1 < NN)
                *(__half2*)(g_hs16 + (size_t)r1 * DD + c) =
                    __floats2half2_rn(acc[mt][j][2], acc[mt][j][3]);
        }
    }
}

// ---------------------------------------------------------------------------
// Gather: one warp per dst node, TWO edges per warp-iteration.
// fp16 rows are 256B = 16 lanes x uint4; halfwarp h handles edge j+h.
// Lane (h,q) accumulates cols [q*8, q*8+8) in fp32; halves combined by shfl.
// MODE 0: +b1, relu, fp16 out to g_h1.  MODE 1: +b2, fp32 out (final).
template <int MODE>
__global__ __launch_bounds__(256)
void gather_kernel(const float* __restrict__ bvec, float* __restrict__ out) {
    const int w    = (blockIdx.x * blockDim.x + threadIdx.x) >> 5;
    const int lane = threadIdx.x & 31;
    const int h    = lane >> 4;       // halfwarp: edge parity
    const int q    = lane & 15;       // uint4 index within row
    if (w >= NN) return;

    const uint4* hs = (const uint4*)g_hs16;   // 16 uint4 per row
    const int start = g_rowptr[w];
    const int n     = g_cnt[w];
    const float di  = g_dinv[w];

    float acc[8] = {0.f, 0.f, 0.f, 0.f, 0.f, 0.f, 0.f, 0.f};

    // self loop: h==0 half only (summed into both at combine)
    if (h == 0) acc8(acc, hs[(size_t)w * 16 + q], di);

    int j = 0;
    for (; j + 4 <= n; j += 4) {               // 4 edges = 2 pair-steps
        int sA = g_srcidx[start + j + h];
        int sB = g_srcidx[start + j + 2 + h];
        float dA = g_dinv[sA], dB = g_dinv[sB];
        uint4 uA = hs[(size_t)sA * 16 + q];
        uint4 uB = hs[(size_t)sB * 16 + q];
        acc8(acc, uA, dA);
        acc8(acc, uB, dB);
    }
    for (; j < n; j += 2) {                    // leftover 1-3 edges, pairwise
        int e = j + h;
        if (e < n) {
            int s = g_srcidx[start + e];
            acc8(acc, hs[(size_t)s * 16 + q], g_dinv[s]);
        }
    }

    // combine halfwarps (both halves end with the full 8-col sums)
    #pragma unroll
    for (int i = 0; i < 8; i++)
        acc[i] += __shfl_xor_sync(0xffffffffu, acc[i], 16);

    // lane stores cols [q*8 + h*4, q*8 + h*4 + 4)
    const float4 bv = ((const float4*)bvec)[q * 2 + h];
    float r0 = acc[h * 4 + 0] * di + bv.x;
    float r1 = acc[h * 4 + 1] * di + bv.y;
    float r2 = acc[h * 4 + 2] * di + bv.z;
    float r3 = acc[h * 4 + 3] * di + bv.w;

    if (MODE == 0) {
        r0 = fmaxf(r0, 0.f); r1 = fmaxf(r1, 0.f);
        r2 = fmaxf(r2, 0.f); r3 = fmaxf(r3, 0.f);
        __half2 p0 = __floats2half2_rn(r0, r1);
        __half2 p1 = __floats2half2_rn(r2, r3);
        uint2 u;
        u.x = *(unsigned*)&p0;
        u.y = *(unsigned*)&p1;
        *(uint2*)(g_h1 + (size_t)w * DD + q * 8 + h * 4) = u;
    } else {
        *(float4*)(out + (size_t)w * DD + q * 8 + h * 4) =
            make_float4(r0, r1, r2, r3);
    }
}

// ---------------------------------------------------------------------------
extern "C" void kernel_launch(void* const* d_in, const int* in_sizes, int n_in,
                              void* d_out, int out_size) {
    const float* x  = (const float*)d_in[0];
    const float* W1 = (const float*)d_in[1];
    const float* b1 = (const float*)d_in[2];
    const float* W2 = (const float*)d_in[3];
    const float* b2 = (const float*)d_in[4];
    const void*  ei = d_in[5];
    float* out = (float*)d_out;

    (void)in_sizes; (void)n_in; (void)out_size;

    cudaFuncSetAttribute(gemm_bf16_kernel<false>,
                         cudaFuncAttributeMaxDynamicSharedMemorySize, GEMM_SMEM);
    cudaFuncSetAttribute(gemm_bf16_kernel<true>,
                         cudaFuncAttributeMaxDynamicSharedMemorySize, GEMM_SMEM);

    const int GEMM_BLOCKS   = (NN + 127) / 128;     // 782
    const int GATHER_BLOCKS = (NN * 32 + 255) / 256;

    // Fork a side stream (capture-legal event fork/join from the default stream).
    cudaStream_t s2;
    cudaStreamCreateWithFlags(&s2, cudaStreamNonBlocking);
    cudaEvent_t evFork, evJoin;
    cudaEventCreateWithFlags(&evFork, cudaEventDisableTiming);
    cudaEventCreateWithFlags(&evJoin, cudaEventDisableTiming);

    cudaEventRecord(evFork, 0);
    cudaStreamWaitEvent(s2, evFork, 0);

    // Branch B (s2): GEMM-1 (independent of CSR/dinv; W converted in-kernel)
    gemm_bf16_kernel<false><<<GEMM_BLOCKS, 256, GEMM_SMEM, s2>>>(x, W1);

    // Branch A (default stream): CSR build
    detect_zero_kernel<<<(NN + 1023) / 1024, 1024>>>((const int*)ei);
    hist_kernel<<<(EE + 255) / 256, 256>>>(ei);
    scan_fused_kernel<<<NBLK_SCAN, 256>>>();
    fill_kernel<<<(EE + 255) / 256, 256>>>(ei);

    // Join
    cudaEventRecord(evJoin, s2);
    cudaStreamWaitEvent(0, evJoin, 0);

    // Layer 1 aggregation -> g_h1 (fp16), then layer 2
    gather_kernel<0><<<GATHER_BLOCKS, 256>>>(b1, out);
    gemm_bf16_kernel<true><<<GEMM_BLOCKS, 256, GEMM_SMEM>>>(nullptr, W2);
    gather_kernel<1><<<GATHER_BLOCKS, 256>>>(b2, out);

    cudaEventDestroy(evFork);
    cudaEventDestroy(evJoin);
}

// round 12
// speedup vs baseline: 1.5991x; 1.1174x over previous
#include <cuda_runtime.h>
#include <cuda_bf16.h>
#include <cuda_fp16.h>
#include <cstdint>

#define NN 100000
#define EE 600000
#define DD 128

#define SCAN_CHUNK 1024
#define NBLK_SCAN ((NN + SCAN_CHUNK - 1) / SCAN_CHUNK)   // 98

// Scratch (allocation-free: __device__ globals)
__device__ __half g_hs16[(size_t)NN * DD]; // GEMM out (raw, no dinv), fp16
__device__ __half g_h1[(size_t)NN * DD];   // layer-1 activations (post relu), fp16
__device__ float g_dinv[NN];
__device__ int   g_cntagg[NN + NBLK_SCAN]; // [0,NN): in-degree; [NN,+98): lookback aggs
__device__ int   g_rowptr[NN];             // CSR row starts
__device__ int   g_fill[NN];               // fill cursors
__device__ int   g_srcidx[EE];             // CSR column (src) indices

// ---------------------------------------------------------------------------
__device__ __forceinline__ uint32_t smem_u32(const void* p) {
    uint32_t a;
    asm("{ .reg .u64 t; cvta.to.shared.u64 t, %1; cvt.u32.u64 %0, t; }"
        : "=r"(a) : "l"(p));
    return a;
}

#define LDMATRIX_X4(r0, r1, r2, r3, addr) \
    asm volatile("ldmatrix.sync.aligned.m8n8.x4.shared.b16 {%0,%1,%2,%3}, [%4];" \
                 : "=r"(r0), "=r"(r1), "=r"(r2), "=r"(r3) : "r"(addr))
#define LDMATRIX_X4_T(r0, r1, r2, r3, addr) \
    asm volatile("ldmatrix.sync.aligned.m8n8.x4.trans.shared.b16 {%0,%1,%2,%3}, [%4];" \
                 : "=r"(r0), "=r"(r1), "=r"(r2), "=r"(r3) : "r"(addr))
#define MMA_BF16(c, a, b) \
    asm volatile("mma.sync.aligned.m16n8k16.row.col.f32.bf16.bf16.f32 " \
                 "{%0,%1,%2,%3}, {%4,%5,%6,%7}, {%8,%9}, {%0,%1,%2,%3};" \
                 : "+f"((c)[0]), "+f"((c)[1]), "+f"((c)[2]), "+f"((c)[3]) \
                 : "r"((a)[0]), "r"((a)[1]), "r"((a)[2]), "r"((a)[3]), \
                   "r"((b)[0]), "r"((b)[1]))
#define MMA_F16(c, a, b) \
    asm volatile("mma.sync.aligned.m16n8k16.row.col.f32.f16.f16.f32 " \
                 "{%0,%1,%2,%3}, {%4,%5,%6,%7}, {%8,%9}, {%0,%1,%2,%3};" \
                 : "+f"((c)[0]), "+f"((c)[1]), "+f"((c)[2]), "+f"((c)[3]) \
                 : "r"((a)[0]), "r"((a)[1]), "r"((a)[2]), "r"((a)[3]), \
                   "r"((b)[0]), "r"((b)[1]))

// Accumulate 8 fp16 cols (uint4) scaled by d into acc[8]
__device__ __forceinline__ void acc8(float* acc, uint4 u, float d) {
    float2 p0 = __half22float2(*(__half2*)&u.x);
    float2 p1 = __half22float2(*(__half2*)&u.y);
    float2 p2 = __half22float2(*(__half2*)&u.z);
    float2 p3 = __half22float2(*(__half2*)&u.w);
    acc[0] = fmaf(p0.x, d, acc[0]);
    acc[1] = fmaf(p0.y, d, acc[1]);
    acc[2] = fmaf(p1.x, d, acc[2]);
    acc[3] = fmaf(p1.y, d, acc[3]);
    acc[4] = fmaf(p2.x, d, acc[4]);
    acc[5] = fmaf(p2.y, d, acc[5]);
    acc[6] = fmaf(p3.x, d, acc[6]);
    acc[7] = fmaf(p3.y, d, acc[7]);
}

// Per-block dtype detection: warp 0 samples 32 odd 32-bit words. For int64
// (little-endian, values < 2^32) they are all zero; for int32 they are random
// edge values (P[all 32 == 0] ~ 1e-160). Result broadcast via shared.
#define DETECT_IS64(ei, s64)                                                 \
    do {                                                                     \
        if (threadIdx.x < 32) {                                              \
            int v = ((const int*)(ei))[2 * (threadIdx.x * 4099) + 1];        \
            unsigned nz = __ballot_sync(0xffffffffu, v != 0);                \
            if (threadIdx.x == 0) (s64) = (nz == 0);                         \
        }                                                                    \
        __syncthreads();                                                     \
    } while (0)

// ---------------------------------------------------------------------------
// Histogram: 2 edges per thread, vectorized paired loads, inline dtype detect.
__global__ __launch_bounds__(256)
void hist_kernel(const void* __restrict__ ei) {
    __shared__ int s64;
    DETECT_IS64(ei, s64);
    const int is64 = s64;
    int e0 = (blockIdx.x * blockDim.x + threadIdx.x) * 2;
    if (e0 >= EE) return;
    int d0, d1;
    if (is64) {
        longlong2 p = ((const longlong2*)((const long long*)ei + EE))[e0 >> 1];
        d0 = (int)p.x; d1 = (int)p.y;
    } else {
        int2 p = ((const int2*)((const int*)ei + EE))[e0 >> 1];
        d0 = p.x; d1 = p.y;
    }
    atomicAdd(&g_cntagg[d0], 1);
    atomicAdd(&g_cntagg[d1], 1);   // EE even -> e0+1 < EE whenever e0 < EE
}

// Fused exclusive scan (decoupled aggregates), finalizes rowptr/fill/dinv.
__global__ __launch_bounds__(256)
void scan_fused_kernel() {
    __shared__ int s_warp[8];
    __shared__ int s_bexcl;
    const int tid  = threadIdx.x;
    const int lane = tid & 31, wid = tid >> 5;
    const int base = blockIdx.x * SCAN_CHUNK + tid * 4;

    int v0 = (base + 0 < NN) ? g_cntagg[base + 0] : 0;
    int v1 = (base + 1 < NN) ? g_cntagg[base + 1] : 0;
    int v2 = (base + 2 < NN) ? g_cntagg[base + 2] : 0;
    int v3 = (base + 3 < NN) ? g_cntagg[base + 3] : 0;
    int tsum = v0 + v1 + v2 + v3;

    int incl = tsum;
    #pragma unroll
    for (int o = 1; o < 32; o <<= 1) {
        int n = __shfl_up_sync(0xffffffffu, incl, o);
        if (lane >= o) incl += n;
    }
    if (lane == 31) s_warp[wid] = incl;
    __syncthreads();
    if (wid == 0) {
        int w = (lane < 8) ? s_warp[lane] : 0;
        int wi = w;
        #pragma unroll
        for (int o = 1; o < 8; o <<= 1) {
            int n = __shfl_up_sync(0xffffffffu, wi, o);
            if (lane >= o) wi += n;
        }
        if (lane < 8) s_warp[lane] = wi - w;
        int btot = __shfl_sync(0xffffffffu, wi, 7);
        if (lane == 0) atomicExch(&g_cntagg[NN + blockIdx.x], btot + 1);

        int sum = 0;
        for (int p = lane; p < blockIdx.x; p += 32) {
            int v;
            do { v = atomicAdd(&g_cntagg[NN + p], 0); } while (v == 0);
            sum += v - 1;
        }
        #pragma unroll
        for (int o = 16; o > 0; o >>= 1)
            sum += __shfl_down_sync(0xffffffffu, sum, o);
        if (lane == 0) s_bexcl = sum;
    }
    __syncthreads();

    int off = s_bexcl + s_warp[wid] + (incl - tsum);
    int o0 = off, o1 = off + v0, o2 = o1 + v1, o3 = o2 + v2;
    if (base + 0 < NN) { g_rowptr[base+0] = o0; g_fill[base+0] = o0; g_dinv[base+0] = rsqrtf((float)(v0 + 1)); }
    if (base + 1 < NN) { g_rowptr[base+1] = o1; g_fill[base+1] = o1; g_dinv[base+1] = rsqrtf((float)(v1 + 1)); }
    if (base + 2 < NN) { g_rowptr[base+2] = o2; g_fill[base+2] = o2; g_dinv[base+2] = rsqrtf((float)(v2 + 1)); }
    if (base + 3 < NN) { g_rowptr[base+3] = o3; g_fill[base+3] = o3; g_dinv[base+3] = rsqrtf((float)(v3 + 1)); }
}

// CSR fill: 2 edges per thread, vectorized paired loads, inline dtype detect.
__global__ __launch_bounds__(256)
void fill_kernel(const void* __restrict__ ei) {
    __shared__ int s64;
    DETECT_IS64(ei, s64);
    const int is64 = s64;
    int e0 = (blockIdx.x * blockDim.x + threadIdx.x) * 2;
    if (e0 >= EE) return;
    int s0, s1, d0, d1;
    if (is64) {
        longlong2 ps = ((const longlong2*)ei)[e0 >> 1];
        longlong2 pd = ((const longlong2*)((const long long*)ei + EE))[e0 >> 1];
        s0 = (int)ps.x; s1 = (int)ps.y;
        d0 = (int)pd.x; d1 = (int)pd.y;
    } else {
        int2 ps = ((const int2*)ei)[e0 >> 1];
        int2 pd = ((const int2*)((const int*)ei + EE))[e0 >> 1];
        s0 = ps.x; s1 = ps.y;
        d0 = pd.x; d1 = pd.y;
    }
    int p0 = atomicAdd(&g_fill[d0], 1);
    g_srcidx[p0] = s0;
    int p1 = atomicAdd(&g_fill[d1], 1);
    g_srcidx[p1] = s1;
}

// ---------------------------------------------------------------------------
// GEMM-1: mma.sync split-bf16, per CTA 128x128 tile, K=128; input X fp32.
// g_hs16[r,:] = fp16( X[r,:] @ W1 )   (raw; dinv applied in gather)
#define XSTR 136
#define SM_XLO 34816
#define SM_WHI 69632
#define SM_WLO 104448
#define GEMM_SMEM 139264

__global__ __launch_bounds__(256, 1)
void gemm_bf16_kernel(const float* __restrict__ Xf, const float* __restrict__ Wf) {
    extern __shared__ __align__(16) char sm[];
    const int tid  = threadIdx.x;
    const int warp = tid >> 5;
    const int lane = tid & 31;
    const int row0 = blockIdx.x * 128;

    // --- W fp32 [K=128][N=128] -> bf16 hi/lo smem images (padded rows) ---
    {
        const float4* wv = (const float4*)Wf;
        #pragma unroll
        for (int i = 0; i < 16; i++) {
            int idx = tid + i * 256;
            int k  = idx >> 5;
            int nc = idx & 31;
            float4 v = wv[idx];
            float f[4] = {v.x, v.y, v.z, v.w};
            unsigned hi[4], lo[4];
            #pragma unroll
            for (int j = 0; j < 4; j++) {
                __nv_bfloat16 h = __float2bfloat16_rn(f[j]);
                float rem = f[j] - __bfloat162float(h);
                __nv_bfloat16 l = __float2bfloat16_rn(rem);
                hi[j] = (unsigned)__bfloat16_as_ushort(h);
                lo[j] = (unsigned)__bfloat16_as_ushort(l);
            }
            int off = k * (XSTR * 2) + nc * 8;
            *(uint2*)(sm + SM_WHI + off) =
                make_uint2(hi[0] | (hi[1] << 16), hi[2] | (hi[3] << 16));
            *(uint2*)(sm + SM_WLO + off) =
                make_uint2(lo[0] | (lo[1] << 16), lo[2] | (lo[3] << 16));
        }
    }
    // --- X tile: fp32 -> bf16 hi/lo, padded rows ---
    {
        int r = tid >> 1;
        int khalf = (tid & 1) * 64;
        bool valid = (row0 + r) < NN;
        const float4* xp = (const float4*)(Xf + (size_t)(row0 + r) * DD);
        #pragma unroll
        for (int kb = 0; kb < 8; kb++) {
            int k = khalf + kb * 8;
            float4 a = valid ? xp[k >> 2] : make_float4(0.f, 0.f, 0.f, 0.f);
            float4 b = valid ? xp[(k >> 2) + 1] : make_float4(0.f, 0.f, 0.f, 0.f);
            float f[8] = {a.x, a.y, a.z, a.w, b.x, b.y, b.z, b.w};
            unsigned hi[8], lo[8];
            #pragma unroll
            for (int j = 0; j < 8; j++) {
                __nv_bfloat16 h = __float2bfloat16_rn(f[j]);
                float rem = f[j] - __bfloat162float(h);
                __nv_bfloat16 l = __float2bfloat16_rn(rem);
                hi[j] = (unsigned)__bfloat16_as_ushort(h);
                lo[j] = (unsigned)__bfloat16_as_ushort(l);
            }
            int off = r * (XSTR * 2) + k * 2;
            *(uint4*)(sm + off) =
                make_uint4(hi[0] | (hi[1] << 16), hi[2] | (hi[3] << 16),
                           hi[4] | (hi[5] << 16), hi[6] | (hi[7] << 16));
            *(uint4*)(sm + SM_XLO + off) =
                make_uint4(lo[0] | (lo[1] << 16), lo[2] | (lo[3] << 16),
                           lo[4] | (lo[5] << 16), lo[6] | (lo[7] << 16));
        }
    }
    __syncthreads();

    const int m_base = (warp >> 1) * 32;
    const int n_base = (warp & 1) * 64;

    const uint32_t sbase = smem_u32(sm);
    const int a_row = (lane & 7) + ((lane >> 3) & 1) * 8;
    const int a_col = (lane >> 4) * 8;
    const int b_krow = (lane & 7) + ((lane >> 3) & 1) * 8;
    const int b_ncol = (lane >> 4) * 8;

    float acc[2][8][4];
    #pragma unroll
    for (int mt = 0; mt < 2; mt++)
        #pragma unroll
        for (int j = 0; j < 8; j++)
            #pragma unroll
            for (int q = 0; q < 4; q++) acc[mt][j][q] = 0.f;

    #pragma unroll 2
    for (int ks = 0; ks < 8; ks++) {
        const int k0 = ks * 16;
        uint32_t ahi[2][4], alo[2][4], bhi[8][2], blo[8][2];
        #pragma unroll
        for (int mt = 0; mt < 2; mt++) {
            uint32_t aoff = ((m_base + mt * 16 + a_row) * XSTR + k0 + a_col) * 2;
            LDMATRIX_X4(ahi[mt][0], ahi[mt][1], ahi[mt][2], ahi[mt][3], sbase + aoff);
            LDMATRIX_X4(alo[mt][0], alo[mt][1], alo[mt][2], alo[mt][3],
                        sbase + SM_XLO + aoff);
        }
        #pragma unroll
        for (int jp = 0; jp < 4; jp++) {
            uint32_t boff = ((k0 + b_krow) * XSTR + n_base + jp * 16 + b_ncol) * 2;
            LDMATRIX_X4_T(bhi[jp * 2][0], bhi[jp * 2][1],
                          bhi[jp * 2 + 1][0], bhi[jp * 2 + 1][1],
                          sbase + SM_WHI + boff);
            LDMATRIX_X4_T(blo[jp * 2][0], blo[jp * 2][1],
                          blo[jp * 2 + 1][0], blo[jp * 2 + 1][1],
                          sbase + SM_WLO + boff);
        }
        #pragma unroll
        for (int mt = 0; mt < 2; mt++)
            #pragma unroll
            for (int j = 0; j < 8; j++) {
                MMA_BF16(acc[mt][j], ahi[mt], bhi[j]);
                MMA_BF16(acc[mt][j], ahi[mt], blo[j]);
                MMA_BF16(acc[mt][j], alo[mt], bhi[j]);
            }
    }

    // --- epilogue: fp16 half2 stores (raw, no dinv) ---
    #pragma unroll
    for (int mt = 0; mt < 2; mt++) {
        int r0 = row0 + m_base + mt * 16 + (lane >> 2);
        int r1 = r0 + 8;
        #pragma unroll
        for (int j = 0; j < 8; j++) {
            int c = n_base + j * 8 + (lane & 3) * 2;
            if (r0 < NN)
                *(__half2*)(g_hs16 + (size_t)r0 * DD + c) =
                    __floats2half2_rn(acc[mt][j][0], acc[mt][j][1]);
            if (r1 < NN)
                *(__half2*)(g_hs16 + (size_t)r1 * DD + c) =
                    __floats2half2_rn(acc[mt][j][2], acc[mt][j][3]);
        }
    }
}

// ---------------------------------------------------------------------------
// GEMM-2: 2-term fp16 MMA. Input g_h1 is fp16-exact, so only W2 is split
// (fp16 hi + fp16 lo = 22 mantissa bits): h1@Whf + h1@Wlf. Error ~2^-22.
// smem: X 34816 + Whf 34816 + Wlf 34816 = 104448 -> occupancy 2.
#define SM2_WHF 34816
#define SM2_WLF 69632
#define GEMM2_SMEM 104448

__global__ __launch_bounds__(256, 2)
void gemm_f16_kernel(const float* __restrict__ Wf) {
    extern __shared__ __align__(16) char sm[];
    const int tid  = threadIdx.x;
    const int warp = tid >> 5;
    const int lane = tid & 31;
    const int row0 = blockIdx.x * 128;

    // --- W fp32 [K=128][N=128] -> fp16 hi/lo smem images (padded rows) ---
    {
        const float4* wv = (const float4*)Wf;
        #pragma unroll
        for (int i = 0; i < 16; i++) {
            int idx = tid + i * 256;
            int k  = idx >> 5;
            int nc = idx & 31;
            float4 v = wv[idx];
            float f[4] = {v.x, v.y, v.z, v.w};
            unsigned hi[4], lo[4];
            #pragma unroll
            for (int j = 0; j < 4; j++) {
                __half h = __float2half_rn(f[j]);
                float rem = f[j] - __half2float(h);
                __half l = __float2half_rn(rem);
                hi[j] = (unsigned)__half_as_ushort(h);
                lo[j] = (unsigned)__half_as_ushort(l);
            }
            int off = k * (XSTR * 2) + nc * 8;
            *(uint2*)(sm + SM2_WHF + off) =
                make_uint2(hi[0] | (hi[1] << 16), hi[2] | (hi[3] << 16));
            *(uint2*)(sm + SM2_WLF + off) =
                make_uint2(lo[0] | (lo[1] << 16), lo[2] | (lo[3] << 16));
        }
    }
    // --- X tile: copy fp16 h1 rows into padded image ---
    {
        int r = tid >> 1;
        int khalf = (tid & 1) * 64;
        bool valid = (row0 + r) < NN;
        const uint4* hp = (const uint4*)(g_h1 + (size_t)(row0 + r) * DD);
        #pragma unroll
        for (int kb = 0; kb < 8; kb++) {
            uint4 u = valid ? hp[(khalf >> 3) + kb] : make_uint4(0u, 0u, 0u, 0u);
            *(uint4*)(sm + r * (XSTR * 2) + khalf * 2 + kb * 16) = u;
        }
    }
    __syncthreads();

    const int m_base = (warp >> 1) * 32;
    const int n_base = (warp & 1) * 64;

    const uint32_t sbase = smem_u32(sm);
    const int a_row = (lane & 7) + ((lane >> 3) & 1) * 8;
    const int a_col = (lane >> 4) * 8;
    const int b_krow = (lane & 7) + ((lane >> 3) & 1) * 8;
    const int b_ncol = (lane >> 4) * 8;

    float acc[2][8][4];
    #pragma unroll
    for (int mt = 0; mt < 2; mt++)
        #pragma unroll
        for (int j = 0; j < 8; j++)
            #pragma unroll
            for (int q = 0; q < 4; q++) acc[mt][j][q] = 0.f;

    #pragma unroll 2
    for (int ks = 0; ks < 8; ks++) {
        const int k0 = ks * 16;
        uint32_t a[2][4], bhf[8][2], blf[8][2];
        #pragma unroll
        for (int mt = 0; mt < 2; mt++) {
            uint32_t aoff = ((m_base + mt * 16 + a_row) * XSTR + k0 + a_col) * 2;
            LDMATRIX_X4(a[mt][0], a[mt][1], a[mt][2], a[mt][3], sbase + aoff);
        }
        #pragma unroll
        for (int jp = 0; jp < 4; jp++) {
            uint32_t boff = ((k0 + b_krow) * XSTR + n_base + jp * 16 + b_ncol) * 2;
            LDMATRIX_X4_T(bhf[jp * 2][0], bhf[jp * 2][1],
                          bhf[jp * 2 + 1][0], bhf[jp * 2 + 1][1],
                          sbase + SM2_WHF + boff);
            LDMATRIX_X4_T(blf[jp * 2][0], blf[jp * 2][1],
                          blf[jp * 2 + 1][0], blf[jp * 2 + 1][1],
                          sbase + SM2_WLF + boff);
        }
        #pragma unroll
        for (int mt = 0; mt < 2; mt++)
            #pragma unroll
            for (int j = 0; j < 8; j++) {
                MMA_F16(acc[mt][j], a[mt], bhf[j]);
                MMA_F16(acc[mt][j], a[mt], blf[j]);
            }
    }

    // --- epilogue: fp16 half2 stores (raw, no dinv) ---
    #pragma unroll
    for (int mt = 0; mt < 2; mt++) {
        int r0 = row0 + m_base + mt * 16 + (lane >> 2);
        int r1 = r0 + 8;
        #pragma unroll
        for (int j = 0; j < 8; j++) {
            int c = n_base + j * 8 + (lane & 3) * 2;
            if (r0 < NN)
                *(__half2*)(g_hs16 + (size_t)r0 * DD + c) =
                    __floats2half2_rn(acc[mt][j][0], acc[mt][j][1]);
            if (r1 < NN)
                *(__half2*)(g_hs16 + (size_t)r1 * DD + c) =
                    __floats2half2_rn(acc[mt][j][2], acc[mt][j][3]);
        }
    }
}

// ---------------------------------------------------------------------------
// Gather: one warp per dst node, TWO edges per warp-iteration (fp16 rows,
// 16 lanes x uint4 per edge). MODE 0: +b1, relu, fp16 -> g_h1. MODE 1: fp32 out.
template <int MODE>
__global__ __launch_bounds__(256)
void gather_kernel(const float* __restrict__ bvec, float* __restrict__ out) {
    const int w    = (blockIdx.x * blockDim.x + threadIdx.x) >> 5;
    const int lane = threadIdx.x & 31;
    const int h    = lane >> 4;
    const int q    = lane & 15;
    if (w >= NN) return;

    const uint4* hs = (const uint4*)g_hs16;
    const int start = g_rowptr[w];
    const int n     = g_cntagg[w];
    const float di  = g_dinv[w];

    float acc[8] = {0.f, 0.f, 0.f, 0.f, 0.f, 0.f, 0.f, 0.f};

    if (h == 0) acc8(acc, hs[(size_t)w * 16 + q], di);   // self loop

    int j = 0;
    for (; j + 4 <= n; j += 4) {
        int sA = g_srcidx[start + j + h];
        int sB = g_srcidx[start + j + 2 + h];
        float dA = g_dinv[sA], dB = g_dinv[sB];
        uint4 uA = hs[(size_t)sA * 16 + q];
        uint4 uB = hs[(size_t)sB * 16 + q];
        acc8(acc, uA, dA);
        acc8(acc, uB, dB);
    }
    for (; j < n; j += 2) {
        int e = j + h;
        if (e < n) {
            int s = g_srcidx[start + e];
            acc8(acc, hs[(size_t)s * 16 + q], g_dinv[s]);
        }
    }

    #pragma unroll
    for (int i = 0; i < 8; i++)
        acc[i] += __shfl_xor_sync(0xffffffffu, acc[i], 16);

    const float4 bv = ((const float4*)bvec)[q * 2 + h];
    float r0 = acc[h * 4 + 0] * di + bv.x;
    float r1 = acc[h * 4 + 1] * di + bv.y;
    float r2 = acc[h * 4 + 2] * di + bv.z;
    float r3 = acc[h * 4 + 3] * di + bv.w;

    if (MODE == 0) {
        r0 = fmaxf(r0, 0.f); r1 = fmaxf(r1, 0.f);
        r2 = fmaxf(r2, 0.f); r3 = fmaxf(r3, 0.f);
        __half2 p0 = __floats2half2_rn(r0, r1);
        __half2 p1 = __floats2half2_rn(r2, r3);
        uint2 u;
        u.x = *(unsigned*)&p0;
        u.y = *(unsigned*)&p1;
        *(uint2*)(g_h1 + (size_t)w * DD + q * 8 + h * 4) = u;
    } else {
        *(float4*)(out + (size_t)w * DD + q * 8 + h * 4) =
            make_float4(r0, r1, r2, r3);
    }
}

// ---------------------------------------------------------------------------
extern "C" void kernel_launch(void* const* d_in, const int* in_sizes, int n_in,
                              void* d_out, int out_size) {
    const float* x  = (const float*)d_in[0];
    const float* W1 = (const float*)d_in[1];
    const float* b1 = (const float*)d_in[2];
    const float* W2 = (const float*)d_in[3];
    const float* b2 = (const float*)d_in[4];
    const void*  ei = d_in[5];
    float* out = (float*)d_out;

    (void)in_sizes; (void)n_in; (void)out_size;

    cudaFuncSetAttribute(gemm_bf16_kernel,
                         cudaFuncAttributeMaxDynamicSharedMemorySize, GEMM_SMEM);
    cudaFuncSetAttribute(gemm_f16_kernel,
                         cudaFuncAttributeMaxDynamicSharedMemorySize, GEMM2_SMEM);

    const int GEMM_BLOCKS   = (NN + 127) / 128;     // 782
    const int GATHER_BLOCKS = (NN * 32 + 255) / 256;
    const int EDGE2_BLOCKS  = (EE / 2 + 255) / 256; // 2 edges/thread

    void* cntagg_ptr = nullptr;
    cudaGetSymbolAddress(&cntagg_ptr, g_cntagg);

    // Fork a side stream (capture-legal event fork/join from the default stream).
    cudaStream_t s2;
    cudaStreamCreateWithFlags(&s2, cudaStreamNonBlocking);
    cudaEvent_t evFork, evJoin;
    cudaEventCreateWithFlags(&evFork, cudaEventDisableTiming);
    cudaEventCreateWithFlags(&evJoin, cudaEventDisableTiming);

    cudaEventRecord(evFork, 0);
    cudaStreamWaitEvent(s2, evFork, 0);

    // Branch B (s2): GEMM-1 (independent of CSR/dinv; W converted in-kernel)
    gemm_bf16_kernel<<<GEMM_BLOCKS, 256, GEMM_SMEM, s2>>>(x, W1);

    // Branch A (default stream): CSR build
    cudaMemsetAsync(cntagg_ptr, 0, (NN + NBLK_SCAN) * sizeof(int), 0);
    hist_kernel<<<EDGE2_BLOCKS, 256>>>(ei);
    scan_fused_kernel<<<NBLK_SCAN, 256>>>();
    fill_kernel<<<EDGE2_BLOCKS, 256>>>(ei);

    // Join
    cudaEventRecord(evJoin, s2);
    cudaStreamWaitEvent(0, evJoin, 0);

    // Layer 1 aggregation -> g_h1 (fp16), then layer 2
    gather_kernel<0><<<GATHER_BLOCKS, 256>>>(b1, out);
    gemm_f16_kernel<<<GEMM_BLOCKS, 256, GEMM2_SMEM>>>(W2);
    gather_kernel<1><<<GATHER_BLOCKS, 256>>>(b2, out);

    cudaEventDestroy(evFork);
    cudaEventDestroy(evJoin);
}